// round 2
// baseline (speedup 1.0000x reference)
#include <cuda_runtime.h>
#include <math.h>

#define BB 4
#define NH 16
#define HD 64
#define ED 1024
#define NQL 1024
#define NKL 2048

// Scratch (no cudaMalloc allowed) ------------------------------------------
__device__ float g_qp[BB * NQL * ED];     // projected Q  [b*nq, 1024]
__device__ float g_kp[BB * NKL * ED];     // projected K  [b*nk, 1024]
__device__ float g_vp[BB * NKL * ED];     // projected V  [b*nk, 1024]
__device__ float g_ao[BB * NQL * ED];     // attention out [b*nq, 1024]
__device__ float g_logm[BB * NKL];        // log multiplicities

// ---------------------------------------------------------------------------
// C[M,N] = A[M,K] @ W[N,K]^T + bias[N]    (both operands K-contiguous)
// 128x128 block tile, 8x8 per-thread microtile, BK=8, 256 threads.
// ---------------------------------------------------------------------------
__global__ __launch_bounds__(256) void gemm_nt_bias(
    const float* __restrict__ A, const float* __restrict__ W,
    const float* __restrict__ bias, float* __restrict__ C,
    int M, int N, int K)
{
    __shared__ float As[8][128];
    __shared__ float Ws[8][128];

    const int tid = threadIdx.x;
    const int bm = blockIdx.y * 128;
    const int bn = blockIdx.x * 128;
    const int tx = tid & 15;
    const int ty = tid >> 4;
    const int lr = tid >> 1;          // 0..127: tile row
    const int lc = (tid & 1) * 4;     // 0 or 4: k sub-chunk

    const float* Ag = A + (size_t)(bm + lr) * K + lc;
    const float* Wg = W + (size_t)(bn + lr) * K + lc;

    float acc[8][8] = {};

    for (int k0 = 0; k0 < K; k0 += 8) {
        float4 av = *(const float4*)(Ag + k0);
        float4 wv = *(const float4*)(Wg + k0);
        As[lc + 0][lr] = av.x; As[lc + 1][lr] = av.y;
        As[lc + 2][lr] = av.z; As[lc + 3][lr] = av.w;
        Ws[lc + 0][lr] = wv.x; Ws[lc + 1][lr] = wv.y;
        Ws[lc + 2][lr] = wv.z; Ws[lc + 3][lr] = wv.w;
        __syncthreads();

        #pragma unroll
        for (int kk = 0; kk < 8; kk++) {
            float4 a0 = *(const float4*)&As[kk][ty * 8];
            float4 a1 = *(const float4*)&As[kk][ty * 8 + 4];
            float4 b0 = *(const float4*)&Ws[kk][tx * 8];
            float4 b1 = *(const float4*)&Ws[kk][tx * 8 + 4];
            float ar[8] = {a0.x, a0.y, a0.z, a0.w, a1.x, a1.y, a1.z, a1.w};
            float br[8] = {b0.x, b0.y, b0.z, b0.w, b1.x, b1.y, b1.z, b1.w};
            #pragma unroll
            for (int i = 0; i < 8; i++)
                #pragma unroll
                for (int j = 0; j < 8; j++)
                    acc[i][j] = fmaf(ar[i], br[j], acc[i][j]);
        }
        __syncthreads();
    }

    #pragma unroll
    for (int i = 0; i < 8; i++) {
        size_t row = (size_t)(bm + ty * 8 + i);
        #pragma unroll
        for (int j = 0; j < 8; j += 4) {
            int col = bn + tx * 8 + j;
            float4 o;
            o.x = acc[i][j + 0] + bias[col + 0];
            o.y = acc[i][j + 1] + bias[col + 1];
            o.z = acc[i][j + 2] + bias[col + 2];
            o.w = acc[i][j + 3] + bias[col + 3];
            *(float4*)&C[row * N + col] = o;
        }
    }
}

// ---------------------------------------------------------------------------
__global__ void logm_kernel(const float* __restrict__ m, float* __restrict__ lm, int n)
{
    int i = blockIdx.x * blockDim.x + threadIdx.x;
    if (i < n) lm[i] = logf(m[i]);
}

// ---------------------------------------------------------------------------
// Flash attention, fp32. One block = (b, h, q-tile of 128). 256 threads.
// Q/K shared as [d][row]; V as [k][d]; P as [q][k]. Online softmax stats in
// registers (warp-level 16-lane reductions; thread's S-rows == its O-rows).
// ---------------------------------------------------------------------------
#define SM_QS 0                      // [64][128]
#define SM_KS (64 * 128)             // [64][128]
#define SM_VS (2 * 64 * 128)         // [128][64]
#define SM_PS (3 * 64 * 128)         // [128][128]
#define SM_LM (3 * 64 * 128 + 128 * 128)
#define SMEM_ATTN_FLOATS (3 * 64 * 128 + 128 * 128 + 128)
#define SMEM_ATTN_BYTES  (SMEM_ATTN_FLOATS * 4)

__global__ __launch_bounds__(256, 1) void attn_kernel(
    const float* __restrict__ Q, const float* __restrict__ Kp,
    const float* __restrict__ Vp, const float* __restrict__ logm,
    float* __restrict__ O)
{
    extern __shared__ float smem[];
    float* Qs = smem + SM_QS;
    float* Ks = smem + SM_KS;
    float* Vs = smem + SM_VS;
    float* Ps = smem + SM_PS;
    float* Lm = smem + SM_LM;

    const int qt = blockIdx.x;   // q tile (0..7)
    const int h  = blockIdx.y;   // head
    const int b  = blockIdx.z;   // batch
    const int tid = threadIdx.x;
    const int tx = tid & 15;
    const int ty = tid >> 4;
    const int q0 = qt * 128;
    const float scale = 0.125f;  // 1/sqrt(64)

    // Load Q tile (pre-scaled), layout Qs[d][q]
    #pragma unroll
    for (int it = 0; it < 8; it++) {
        int idx = tid + it * 256;          // 0..2047 float4s
        int row = idx >> 4;                // 0..127
        int c4  = (idx & 15) << 2;         // 0..60
        float4 v = *(const float4*)&Q[(size_t)(b * NQL + q0 + row) * ED + h * HD + c4];
        Qs[(c4 + 0) * 128 + row] = v.x * scale;
        Qs[(c4 + 1) * 128 + row] = v.y * scale;
        Qs[(c4 + 2) * 128 + row] = v.z * scale;
        Qs[(c4 + 3) * 128 + row] = v.w * scale;
    }

    float m_i[8], l_i[8];
    #pragma unroll
    for (int i = 0; i < 8; i++) { m_i[i] = -1e30f; l_i[i] = 0.0f; }
    float o_acc[8][4] = {};

    for (int k0 = 0; k0 < NKL; k0 += 128) {
        // Load K tile ([d][k]) and V tile ([k][d])
        #pragma unroll
        for (int it = 0; it < 8; it++) {
            int idx = tid + it * 256;
            int row = idx >> 4;
            int c4  = (idx & 15) << 2;
            size_t base = (size_t)(b * NKL + k0 + row) * ED + h * HD + c4;
            float4 kv = *(const float4*)&Kp[base];
            Ks[(c4 + 0) * 128 + row] = kv.x;
            Ks[(c4 + 1) * 128 + row] = kv.y;
            Ks[(c4 + 2) * 128 + row] = kv.z;
            Ks[(c4 + 3) * 128 + row] = kv.w;
            float4 vv = *(const float4*)&Vp[base];
            *(float4*)&Vs[row * 64 + c4] = vv;
        }
        if (tid < 128) Lm[tid] = logm[b * NKL + k0 + tid];
        __syncthreads();

        // S = Q^T K  (rows ty*8+i, cols tx*8+j)
        float s[8][8] = {};
        #pragma unroll 8
        for (int dd = 0; dd < 64; dd++) {
            float4 a0 = *(const float4*)&Qs[dd * 128 + ty * 8];
            float4 a1 = *(const float4*)&Qs[dd * 128 + ty * 8 + 4];
            float4 b0 = *(const float4*)&Ks[dd * 128 + tx * 8];
            float4 b1 = *(const float4*)&Ks[dd * 128 + tx * 8 + 4];
            float ar[8] = {a0.x, a0.y, a0.z, a0.w, a1.x, a1.y, a1.z, a1.w};
            float br[8] = {b0.x, b0.y, b0.z, b0.w, b1.x, b1.y, b1.z, b1.w};
            #pragma unroll
            for (int i = 0; i < 8; i++)
                #pragma unroll
                for (int j = 0; j < 8; j++)
                    s[i][j] = fmaf(ar[i], br[j], s[i][j]);
        }

        // logits += log multiplicities; online softmax
        float lm8[8];
        #pragma unroll
        for (int j = 0; j < 8; j++) lm8[j] = Lm[tx * 8 + j];

        #pragma unroll
        for (int i = 0; i < 8; i++) {
            float rm = -1e30f;
            #pragma unroll
            for (int j = 0; j < 8; j++) {
                s[i][j] += lm8[j];
                rm = fmaxf(rm, s[i][j]);
            }
            #pragma unroll
            for (int off = 8; off >= 1; off >>= 1)
                rm = fmaxf(rm, __shfl_xor_sync(0xffffffffu, rm, off));
            float mn = fmaxf(m_i[i], rm);
            float alpha = __expf(m_i[i] - mn);
            m_i[i] = mn;
            float rs = 0.0f;
            #pragma unroll
            for (int j = 0; j < 8; j++) {
                float p = __expf(s[i][j] - mn);
                s[i][j] = p;
                rs += p;
            }
            #pragma unroll
            for (int off = 8; off >= 1; off >>= 1)
                rs += __shfl_xor_sync(0xffffffffu, rs, off);
            l_i[i] = l_i[i] * alpha + rs;
            #pragma unroll
            for (int jj = 0; jj < 4; jj++) o_acc[i][jj] *= alpha;
        }

        // store P to shared, layout Ps[q][k]
        #pragma unroll
        for (int i = 0; i < 8; i++) {
            float4 p0 = make_float4(s[i][0], s[i][1], s[i][2], s[i][3]);
            float4 p1 = make_float4(s[i][4], s[i][5], s[i][6], s[i][7]);
            *(float4*)&Ps[(ty * 8 + i) * 128 + tx * 8]     = p0;
            *(float4*)&Ps[(ty * 8 + i) * 128 + tx * 8 + 4] = p1;
        }
        __syncthreads();

        // O += P @ V   (O rows ty*8+i, cols tx*4+jj)
        #pragma unroll 4
        for (int kk = 0; kk < 128; kk += 4) {
            float4 a4[8];
            #pragma unroll
            for (int i = 0; i < 8; i++)
                a4[i] = *(const float4*)&Ps[(ty * 8 + i) * 128 + kk];
            float4 b4[4];
            #pragma unroll
            for (int t = 0; t < 4; t++)
                b4[t] = *(const float4*)&Vs[(kk + t) * 64 + tx * 4];
            #pragma unroll
            for (int i = 0; i < 8; i++) {
                float at[4] = {a4[i].x, a4[i].y, a4[i].z, a4[i].w};
                #pragma unroll
                for (int t = 0; t < 4; t++) {
                    o_acc[i][0] = fmaf(at[t], b4[t].x, o_acc[i][0]);
                    o_acc[i][1] = fmaf(at[t], b4[t].y, o_acc[i][1]);
                    o_acc[i][2] = fmaf(at[t], b4[t].z, o_acc[i][2]);
                    o_acc[i][3] = fmaf(at[t], b4[t].w, o_acc[i][3]);
                }
            }
        }
        __syncthreads();
    }

    // Normalize and write out (merged-head layout)
    #pragma unroll
    for (int i = 0; i < 8; i++) {
        int q = q0 + ty * 8 + i;
        float inv = 1.0f / l_i[i];
        float4 o;
        o.x = o_acc[i][0] * inv;
        o.y = o_acc[i][1] * inv;
        o.z = o_acc[i][2] * inv;
        o.w = o_acc[i][3] * inv;
        *(float4*)&O[(size_t)(b * NQL + q) * ED + h * HD + tx * 4] = o;
    }
}

// ---------------------------------------------------------------------------
extern "C" void kernel_launch(void* const* d_in, const int* in_sizes, int n_in,
                              void* d_out, int out_size)
{
    const float* query = (const float*)d_in[0];
    const float* key   = (const float*)d_in[1];
    const float* value = (const float*)d_in[2];
    const float* kmult = (const float*)d_in[3];
    const float* wq_w  = (const float*)d_in[4];
    const float* wq_b  = (const float*)d_in[5];
    const float* wk_w  = (const float*)d_in[6];
    const float* wk_b  = (const float*)d_in[7];
    const float* wv_w  = (const float*)d_in[8];
    const float* wv_b  = (const float*)d_in[9];
    const float* wo_w  = (const float*)d_in[10];
    const float* wo_b  = (const float*)d_in[11];
    float* out = (float*)d_out;

    float *qp, *kp, *vp, *ao, *lm;
    cudaGetSymbolAddress((void**)&qp, g_qp);
    cudaGetSymbolAddress((void**)&kp, g_kp);
    cudaGetSymbolAddress((void**)&vp, g_vp);
    cudaGetSymbolAddress((void**)&ao, g_ao);
    cudaGetSymbolAddress((void**)&lm, g_logm);

    cudaFuncSetAttribute(attn_kernel,
                         cudaFuncAttributeMaxDynamicSharedMemorySize,
                         SMEM_ATTN_BYTES);

    // Projections
    {
        dim3 blk(256);
        dim3 gq(ED / 128, (BB * NQL) / 128);   // (8, 32)
        dim3 gk(ED / 128, (BB * NKL) / 128);   // (8, 64)
        gemm_nt_bias<<<gq, blk>>>(query, wq_w, wq_b, qp, BB * NQL, ED, ED);
        gemm_nt_bias<<<gk, blk>>>(key,   wk_w, wk_b, kp, BB * NKL, ED, ED);
        gemm_nt_bias<<<gk, blk>>>(value, wv_w, wv_b, vp, BB * NKL, ED, ED);
    }

    // log multiplicities
    logm_kernel<<<(BB * NKL + 255) / 256, 256>>>(kmult, lm, BB * NKL);

    // Attention
    {
        dim3 grid(NQL / 128, NH, BB);   // (8, 16, 4)
        attn_kernel<<<grid, 256, SMEM_ATTN_BYTES>>>(qp, kp, vp, lm, ao);
    }

    // Output projection
    {
        dim3 blk(256);
        dim3 go(ED / 128, (BB * NQL) / 128);
        gemm_nt_bias<<<go, blk>>>(ao, wo_w, wo_b, out, BB * NQL, ED, ED);
    }
}

// round 5
// speedup vs baseline: 1.6827x; 1.6827x over previous
#include <cuda_runtime.h>
#include <cuda_bf16.h>
#include <math.h>
#include <stdint.h>

#define BB 4
#define NH 16
#define HD 64
#define ED 1024
#define NQL 1024
#define NKL 2048

// ---------------------------------------------------------------------------
// Scratch (no cudaMalloc allowed)
// ---------------------------------------------------------------------------
__device__ float g_qp[BB * NQL * ED];     // projected Q  [b*nq, 1024] fp32
__device__ float g_kp[BB * NKL * ED];     // projected K
__device__ float g_vp[BB * NKL * ED];     // projected V
__device__ float g_ao[BB * NQL * ED];     // attention out fp32
__device__ float g_logm[BB * NKL];        // log multiplicities

// bf16 split operands
__device__ __nv_bfloat16 g_xq_h[BB * NQL * ED], g_xq_l[BB * NQL * ED];
__device__ __nv_bfloat16 g_xk_h[BB * NKL * ED], g_xk_l[BB * NKL * ED];
__device__ __nv_bfloat16 g_xv_h[BB * NKL * ED], g_xv_l[BB * NKL * ED];
__device__ __nv_bfloat16 g_ao_h[BB * NQL * ED], g_ao_l[BB * NQL * ED];
__device__ __nv_bfloat16 g_w_h[4 * ED * ED],    g_w_l[4 * ED * ED];

// single dynamic-smem symbol for the whole TU
extern __shared__ char dyn_smem[];

// ---------------------------------------------------------------------------
// helpers
// ---------------------------------------------------------------------------
__device__ __forceinline__ uint32_t smem_u32(const void* p) {
    uint32_t a;
    asm("{ .reg .u64 t; cvta.to.shared.u64 t, %1; cvt.u32.u64 %0, t; }"
        : "=r"(a) : "l"(p));
    return a;
}
__device__ __forceinline__ void cp16(uint32_t dst, const void* src) {
    asm volatile("cp.async.cg.shared.global [%0], [%1], 16;"
                 :: "r"(dst), "l"(src));
}
__device__ __forceinline__ void cp_commit() {
    asm volatile("cp.async.commit_group;");
}
__device__ __forceinline__ void cp_wait1() {
    asm volatile("cp.async.wait_group 1;" ::: "memory");
}
__device__ __forceinline__ void cp_wait0() {
    asm volatile("cp.async.wait_group 0;" ::: "memory");
}
__device__ __forceinline__ void ldsm4(uint32_t* r, uint32_t addr) {
    asm volatile("ldmatrix.sync.aligned.m8n8.x4.shared.b16 {%0,%1,%2,%3}, [%4];"
                 : "=r"(r[0]), "=r"(r[1]), "=r"(r[2]), "=r"(r[3]) : "r"(addr));
}
__device__ __forceinline__ void mma16816(float* c, const uint32_t* a, const uint32_t* b) {
    asm volatile(
        "mma.sync.aligned.m16n8k16.row.col.f32.bf16.bf16.f32 "
        "{%0,%1,%2,%3}, {%4,%5,%6,%7}, {%8,%9}, {%0,%1,%2,%3};"
        : "+f"(c[0]), "+f"(c[1]), "+f"(c[2]), "+f"(c[3])
        : "r"(a[0]), "r"(a[1]), "r"(a[2]), "r"(a[3]), "r"(b[0]), "r"(b[1]));
}

// ---------------------------------------------------------------------------
// split-bf16 HMMA GEMM:  C[M,1024] = A[M,1024] @ W[1024,1024]^T + bias
// C += Ah*Wh^T + Ah*Wl^T + Al*Wh^T   (fp32 accumulators in registers)
// CTA tile 128x128, 8 warps (4m x 2n), warp tile 32x64, BK=64 double-buffered.
// SMEM layout per matrix tile: row-major 128 rows x 128B, 16B groups XOR-swizzled
// by row&7 -> conflict-free for both cp.async stores and ldmatrix loads.
// ---------------------------------------------------------------------------
#define GBM 128
#define GBN 128
#define GBK 64
#define GNCH (ED / GBK)             // 16
#define TILE_B (GBM * GBK * 2)      // 16384 bytes
#define OFF_AH 0
#define OFF_AL (1 * TILE_B)
#define OFF_WH (2 * TILE_B)
#define OFF_WL (3 * TILE_B)
#define GBUF_B (4 * TILE_B)         // 65536
#define GEMM_SMEM (2 * GBUF_B)      // 131072

__device__ __forceinline__ void g_load_chunk(
    uint32_t buf, int tid, int bm, int bn, int k0,
    const __nv_bfloat16* __restrict__ Ah, const __nv_bfloat16* __restrict__ Al,
    const __nv_bfloat16* __restrict__ Wh, const __nv_bfloat16* __restrict__ Wl)
{
    #pragma unroll
    for (int i = 0; i < 4; i++) {
        int g   = tid + i * 256;        // 0..1023
        int row = g >> 3, kg = g & 7;
        uint32_t so = (uint32_t)(row * 128 + ((kg ^ (row & 7)) << 4));
        size_t ga = (size_t)(bm + row) * ED + k0 + kg * 8;
        size_t gw = (size_t)(bn + row) * ED + k0 + kg * 8;
        cp16(buf + OFF_AH + so, Ah + ga);
        cp16(buf + OFF_AL + so, Al + ga);
        cp16(buf + OFF_WH + so, Wh + gw);
        cp16(buf + OFF_WL + so, Wl + gw);
    }
    cp_commit();
}

__global__ __launch_bounds__(256, 1) void gemm_mma(
    const __nv_bfloat16* __restrict__ Ah, const __nv_bfloat16* __restrict__ Al,
    const __nv_bfloat16* __restrict__ Wh, const __nv_bfloat16* __restrict__ Wl,
    const float* __restrict__ bias, float* __restrict__ C)
{
    const uint32_t sb = smem_u32(dyn_smem);
    const int tid  = threadIdx.x;
    const int wid  = tid >> 5, lane = tid & 31;
    const int wm   = wid & 3, wn = wid >> 2;
    const int m0   = wm * 32, n0 = wn * 64;
    const int bm   = blockIdx.y * GBM;
    const int bn   = blockIdx.x * GBN;

    float acc[2][8][4];
    #pragma unroll
    for (int a = 0; a < 2; a++)
        #pragma unroll
        for (int b = 0; b < 8; b++)
            #pragma unroll
            for (int c = 0; c < 4; c++) acc[a][b][c] = 0.0f;

    // precomputed ldmatrix lane addressing
    const int rowA_in = (lane & 15);           // within 16-row tile
    const int khA     = lane >> 4;             // 0/1 -> k half
    const int nrow_in = ((lane & 16) >> 1) + (lane & 7);  // 0..15 within 16-n group
    const int khB     = (lane >> 3) & 1;

    g_load_chunk(sb, tid, bm, bn, 0, Ah, Al, Wh, Wl);

    for (int ch = 0; ch < GNCH; ch++) {
        const uint32_t cur = sb + (uint32_t)(ch & 1) * GBUF_B;
        if (ch + 1 < GNCH) {
            g_load_chunk(sb + (uint32_t)((ch + 1) & 1) * GBUF_B, tid, bm, bn,
                         (ch + 1) * GBK, Ah, Al, Wh, Wl);
            cp_wait1();
        } else {
            cp_wait0();
        }
        __syncthreads();

        #pragma unroll
        for (int k16 = 0; k16 < 4; k16++) {
            uint32_t ah[2][4], al[2][4];
            const int kgA = k16 * 2 + khA;
            #pragma unroll
            for (int mt = 0; mt < 2; mt++) {
                int rA = m0 + mt * 16 + rowA_in;
                uint32_t off = (uint32_t)(rA * 128 + ((kgA ^ (rA & 7)) << 4));
                ldsm4(ah[mt], cur + OFF_AH + off);
                ldsm4(al[mt], cur + OFF_AL + off);
            }
            const int kgB = k16 * 2 + khB;
            #pragma unroll
            for (int g = 0; g < 4; g++) {
                int nr = n0 + g * 16 + nrow_in;
                uint32_t off = (uint32_t)(nr * 128 + ((kgB ^ (nr & 7)) << 4));
                uint32_t bh[4], bl[4];
                ldsm4(bh, cur + OFF_WH + off);
                ldsm4(bl, cur + OFF_WL + off);
                #pragma unroll
                for (int mt = 0; mt < 2; mt++) {
                    mma16816(acc[mt][g * 2 + 0], ah[mt], &bh[0]);
                    mma16816(acc[mt][g * 2 + 0], ah[mt], &bl[0]);
                    mma16816(acc[mt][g * 2 + 0], al[mt], &bh[0]);
                    mma16816(acc[mt][g * 2 + 1], ah[mt], &bh[2]);
                    mma16816(acc[mt][g * 2 + 1], ah[mt], &bl[2]);
                    mma16816(acc[mt][g * 2 + 1], al[mt], &bh[2]);
                }
            }
        }
        __syncthreads();
    }

    // epilogue
    const int lr = lane >> 2;
    const int lc = (lane & 3) * 2;
    #pragma unroll
    for (int mt = 0; mt < 2; mt++) {
        #pragma unroll
        for (int nt = 0; nt < 8; nt++) {
            int row = bm + m0 + mt * 16 + lr;
            int col = bn + n0 + nt * 8 + lc;
            float2 b2 = *(const float2*)&bias[col];
            float2 v0, v1;
            v0.x = acc[mt][nt][0] + b2.x;
            v0.y = acc[mt][nt][1] + b2.y;
            v1.x = acc[mt][nt][2] + b2.x;
            v1.y = acc[mt][nt][3] + b2.y;
            *(float2*)&C[(size_t)row * ED + col]       = v0;
            *(float2*)&C[(size_t)(row + 8) * ED + col] = v1;
        }
    }
}

// ---------------------------------------------------------------------------
// fp32 -> bf16 hi/lo split conversion
// ---------------------------------------------------------------------------
__global__ void split4_kernel(const float* __restrict__ x,
                              __nv_bfloat16* __restrict__ hi,
                              __nv_bfloat16* __restrict__ lo, int n4)
{
    int i = blockIdx.x * blockDim.x + threadIdx.x;
    if (i >= n4) return;
    float4 v = ((const float4*)x)[i];
    __nv_bfloat16 h0 = __float2bfloat16(v.x);
    __nv_bfloat16 h1 = __float2bfloat16(v.y);
    __nv_bfloat16 h2 = __float2bfloat16(v.z);
    __nv_bfloat16 h3 = __float2bfloat16(v.w);
    __nv_bfloat16 l0 = __float2bfloat16(v.x - __bfloat162float(h0));
    __nv_bfloat16 l1 = __float2bfloat16(v.y - __bfloat162float(h1));
    __nv_bfloat16 l2 = __float2bfloat16(v.z - __bfloat162float(h2));
    __nv_bfloat16 l3 = __float2bfloat16(v.w - __bfloat162float(h3));
    ((__nv_bfloat162*)hi)[2 * i]     = __nv_bfloat162(h0, h1);
    ((__nv_bfloat162*)hi)[2 * i + 1] = __nv_bfloat162(h2, h3);
    ((__nv_bfloat162*)lo)[2 * i]     = __nv_bfloat162(l0, l1);
    ((__nv_bfloat162*)lo)[2 * i + 1] = __nv_bfloat162(l2, l3);
}

__global__ void wsplit_kernel(const float* __restrict__ w0, const float* __restrict__ w1,
                              const float* __restrict__ w2, const float* __restrict__ w3,
                              __nv_bfloat16* __restrict__ hi,
                              __nv_bfloat16* __restrict__ lo)
{
    int i = blockIdx.x * blockDim.x + threadIdx.x;
    if (i >= 4 * ED * ED / 4) return;
    int which = i >> 18;
    int off = i & 262143;
    const float* w = which == 0 ? w0 : which == 1 ? w1 : which == 2 ? w2 : w3;
    float4 v = ((const float4*)w)[off];
    __nv_bfloat16 h0 = __float2bfloat16(v.x);
    __nv_bfloat16 h1 = __float2bfloat16(v.y);
    __nv_bfloat16 h2 = __float2bfloat16(v.z);
    __nv_bfloat16 h3 = __float2bfloat16(v.w);
    __nv_bfloat16 l0 = __float2bfloat16(v.x - __bfloat162float(h0));
    __nv_bfloat16 l1 = __float2bfloat16(v.y - __bfloat162float(h1));
    __nv_bfloat16 l2 = __float2bfloat16(v.z - __bfloat162float(h2));
    __nv_bfloat16 l3 = __float2bfloat16(v.w - __bfloat162float(h3));
    ((__nv_bfloat162*)hi)[2 * i]     = __nv_bfloat162(h0, h1);
    ((__nv_bfloat162*)hi)[2 * i + 1] = __nv_bfloat162(h2, h3);
    ((__nv_bfloat162*)lo)[2 * i]     = __nv_bfloat162(l0, l1);
    ((__nv_bfloat162*)lo)[2 * i + 1] = __nv_bfloat162(l2, l3);
}

// ---------------------------------------------------------------------------
__global__ void logm_kernel(const float* __restrict__ m, float* __restrict__ lm, int n)
{
    int i = blockIdx.x * blockDim.x + threadIdx.x;
    if (i < n) lm[i] = logf(m[i]);
}

// ---------------------------------------------------------------------------
// Flash attention, fp32 (known-good; port to HMMA next round)
// ---------------------------------------------------------------------------
#define SM_QS 0
#define SM_KS (64 * 128)
#define SM_VS (2 * 64 * 128)
#define SM_PS (3 * 64 * 128)
#define SM_LM (3 * 64 * 128 + 128 * 128)
#define SMEM_ATTN_FLOATS (3 * 64 * 128 + 128 * 128 + 128)
#define SMEM_ATTN_BYTES  (SMEM_ATTN_FLOATS * 4)

__global__ __launch_bounds__(256, 1) void attn_kernel(
    const float* __restrict__ Q, const float* __restrict__ Kp,
    const float* __restrict__ Vp, const float* __restrict__ logm,
    float* __restrict__ O)
{
    float* smem = (float*)dyn_smem;
    float* Qs = smem + SM_QS;
    float* Ks = smem + SM_KS;
    float* Vs = smem + SM_VS;
    float* Ps = smem + SM_PS;
    float* Lm = smem + SM_LM;

    const int qt = blockIdx.x;
    const int h  = blockIdx.y;
    const int b  = blockIdx.z;
    const int tid = threadIdx.x;
    const int tx = tid & 15;
    const int ty = tid >> 4;
    const int q0 = qt * 128;
    const float scale = 0.125f;

    #pragma unroll
    for (int it = 0; it < 8; it++) {
        int idx = tid + it * 256;
        int row = idx >> 4;
        int c4  = (idx & 15) << 2;
        float4 v = *(const float4*)&Q[(size_t)(b * NQL + q0 + row) * ED + h * HD + c4];
        Qs[(c4 + 0) * 128 + row] = v.x * scale;
        Qs[(c4 + 1) * 128 + row] = v.y * scale;
        Qs[(c4 + 2) * 128 + row] = v.z * scale;
        Qs[(c4 + 3) * 128 + row] = v.w * scale;
    }

    float m_i[8], l_i[8];
    #pragma unroll
    for (int i = 0; i < 8; i++) { m_i[i] = -1e30f; l_i[i] = 0.0f; }
    float o_acc[8][4] = {};

    for (int k0 = 0; k0 < NKL; k0 += 128) {
        #pragma unroll
        for (int it = 0; it < 8; it++) {
            int idx = tid + it * 256;
            int row = idx >> 4;
            int c4  = (idx & 15) << 2;
            size_t base = (size_t)(b * NKL + k0 + row) * ED + h * HD + c4;
            float4 kv = *(const float4*)&Kp[base];
            Ks[(c4 + 0) * 128 + row] = kv.x;
            Ks[(c4 + 1) * 128 + row] = kv.y;
            Ks[(c4 + 2) * 128 + row] = kv.z;
            Ks[(c4 + 3) * 128 + row] = kv.w;
            float4 vv = *(const float4*)&Vp[base];
            *(float4*)&Vs[row * 64 + c4] = vv;
        }
        if (tid < 128) Lm[tid] = logm[b * NKL + k0 + tid];
        __syncthreads();

        float s[8][8] = {};
        #pragma unroll 8
        for (int dd = 0; dd < 64; dd++) {
            float4 a0 = *(const float4*)&Qs[dd * 128 + ty * 8];
            float4 a1 = *(const float4*)&Qs[dd * 128 + ty * 8 + 4];
            float4 b0 = *(const float4*)&Ks[dd * 128 + tx * 8];
            float4 b1 = *(const float4*)&Ks[dd * 128 + tx * 8 + 4];
            float ar[8] = {a0.x, a0.y, a0.z, a0.w, a1.x, a1.y, a1.z, a1.w};
            float br[8] = {b0.x, b0.y, b0.z, b0.w, b1.x, b1.y, b1.z, b1.w};
            #pragma unroll
            for (int i = 0; i < 8; i++)
                #pragma unroll
                for (int j = 0; j < 8; j++)
                    s[i][j] = fmaf(ar[i], br[j], s[i][j]);
        }

        float lm8[8];
        #pragma unroll
        for (int j = 0; j < 8; j++) lm8[j] = Lm[tx * 8 + j];

        #pragma unroll
        for (int i = 0; i < 8; i++) {
            float rm = -1e30f;
            #pragma unroll
            for (int j = 0; j < 8; j++) {
                s[i][j] += lm8[j];
                rm = fmaxf(rm, s[i][j]);
            }
            #pragma unroll
            for (int off = 8; off >= 1; off >>= 1)
                rm = fmaxf(rm, __shfl_xor_sync(0xffffffffu, rm, off));
            float mn = fmaxf(m_i[i], rm);
            float alpha = __expf(m_i[i] - mn);
            m_i[i] = mn;
            float rs = 0.0f;
            #pragma unroll
            for (int j = 0; j < 8; j++) {
                float p = __expf(s[i][j] - mn);
                s[i][j] = p;
                rs += p;
            }
            #pragma unroll
            for (int off = 8; off >= 1; off >>= 1)
                rs += __shfl_xor_sync(0xffffffffu, rs, off);
            l_i[i] = l_i[i] * alpha + rs;
            #pragma unroll
            for (int jj = 0; jj < 4; jj++) o_acc[i][jj] *= alpha;
        }

        #pragma unroll
        for (int i = 0; i < 8; i++) {
            float4 p0 = make_float4(s[i][0], s[i][1], s[i][2], s[i][3]);
            float4 p1 = make_float4(s[i][4], s[i][5], s[i][6], s[i][7]);
            *(float4*)&Ps[(ty * 8 + i) * 128 + tx * 8]     = p0;
            *(float4*)&Ps[(ty * 8 + i) * 128 + tx * 8 + 4] = p1;
        }
        __syncthreads();

        #pragma unroll 4
        for (int kk = 0; kk < 128; kk += 4) {
            float4 a4[8];
            #pragma unroll
            for (int i = 0; i < 8; i++)
                a4[i] = *(const float4*)&Ps[(ty * 8 + i) * 128 + kk];
            float4 b4[4];
            #pragma unroll
            for (int t = 0; t < 4; t++)
                b4[t] = *(const float4*)&Vs[(kk + t) * 64 + tx * 4];
            #pragma unroll
            for (int i = 0; i < 8; i++) {
                float at[4] = {a4[i].x, a4[i].y, a4[i].z, a4[i].w};
                #pragma unroll
                for (int t = 0; t < 4; t++) {
                    o_acc[i][0] = fmaf(at[t], b4[t].x, o_acc[i][0]);
                    o_acc[i][1] = fmaf(at[t], b4[t].y, o_acc[i][1]);
                    o_acc[i][2] = fmaf(at[t], b4[t].z, o_acc[i][2]);
                    o_acc[i][3] = fmaf(at[t], b4[t].w, o_acc[i][3]);
                }
            }
        }
        __syncthreads();
    }

    #pragma unroll
    for (int i = 0; i < 8; i++) {
        int q = q0 + ty * 8 + i;
        float inv = 1.0f / l_i[i];
        float4 o;
        o.x = o_acc[i][0] * inv;
        o.y = o_acc[i][1] * inv;
        o.z = o_acc[i][2] * inv;
        o.w = o_acc[i][3] * inv;
        *(float4*)&O[(size_t)(b * NQL + q) * ED + h * HD + tx * 4] = o;
    }
}

// ---------------------------------------------------------------------------
extern "C" void kernel_launch(void* const* d_in, const int* in_sizes, int n_in,
                              void* d_out, int out_size)
{
    const float* query = (const float*)d_in[0];
    const float* key   = (const float*)d_in[1];
    const float* value = (const float*)d_in[2];
    const float* kmult = (const float*)d_in[3];
    const float* wq_w  = (const float*)d_in[4];
    const float* wq_b  = (const float*)d_in[5];
    const float* wk_w  = (const float*)d_in[6];
    const float* wk_b  = (const float*)d_in[7];
    const float* wv_w  = (const float*)d_in[8];
    const float* wv_b  = (const float*)d_in[9];
    const float* wo_w  = (const float*)d_in[10];
    const float* wo_b  = (const float*)d_in[11];
    float* out = (float*)d_out;

    float *qp, *kp, *vp, *ao, *lm;
    cudaGetSymbolAddress((void**)&qp, g_qp);
    cudaGetSymbolAddress((void**)&kp, g_kp);
    cudaGetSymbolAddress((void**)&vp, g_vp);
    cudaGetSymbolAddress((void**)&ao, g_ao);
    cudaGetSymbolAddress((void**)&lm, g_logm);
    __nv_bfloat16 *xqh, *xql, *xkh, *xkl, *xvh, *xvl, *aoh, *aol, *wh, *wl;
    cudaGetSymbolAddress((void**)&xqh, g_xq_h);
    cudaGetSymbolAddress((void**)&xql, g_xq_l);
    cudaGetSymbolAddress((void**)&xkh, g_xk_h);
    cudaGetSymbolAddress((void**)&xkl, g_xk_l);
    cudaGetSymbolAddress((void**)&xvh, g_xv_h);
    cudaGetSymbolAddress((void**)&xvl, g_xv_l);
    cudaGetSymbolAddress((void**)&aoh, g_ao_h);
    cudaGetSymbolAddress((void**)&aol, g_ao_l);
    cudaGetSymbolAddress((void**)&wh,  g_w_h);
    cudaGetSymbolAddress((void**)&wl,  g_w_l);

    cudaFuncSetAttribute(attn_kernel,
                         cudaFuncAttributeMaxDynamicSharedMemorySize,
                         SMEM_ATTN_BYTES);
    cudaFuncSetAttribute(gemm_mma,
                         cudaFuncAttributeMaxDynamicSharedMemorySize,
                         GEMM_SMEM);

    const int NQ4 = BB * NQL * ED / 4;
    const int NK4 = BB * NKL * ED / 4;

    // hi/lo conversions
    split4_kernel<<<(NQ4 + 255) / 256, 256>>>(query, xqh, xql, NQ4);
    split4_kernel<<<(NK4 + 255) / 256, 256>>>(key,   xkh, xkl, NK4);
    split4_kernel<<<(NK4 + 255) / 256, 256>>>(value, xvh, xvl, NK4);
    wsplit_kernel<<<(4 * ED * ED / 4 + 255) / 256, 256>>>(wq_w, wk_w, wv_w, wo_w, wh, wl);
    logm_kernel<<<(BB * NKL + 255) / 256, 256>>>(kmult, lm, BB * NKL);

    // Q/K/V projections (tensor cores via mma.sync)
    {
        dim3 blk(256);
        dim3 gq(ED / GBN, (BB * NQL) / GBM);   // (8, 32)
        dim3 gk(ED / GBN, (BB * NKL) / GBM);   // (8, 64)
        gemm_mma<<<gq, blk, GEMM_SMEM>>>(xqh, xql, wh + 0 * ED * ED, wl + 0 * ED * ED, wq_b, qp);
        gemm_mma<<<gk, blk, GEMM_SMEM>>>(xkh, xkl, wh + 1 * ED * ED, wl + 1 * ED * ED, wk_b, kp);
        gemm_mma<<<gk, blk, GEMM_SMEM>>>(xvh, xvl, wh + 2 * ED * ED, wl + 2 * ED * ED, wv_b, vp);
    }

    // attention (fp32 flash)
    {
        dim3 grid(NQL / 128, NH, BB);
        attn_kernel<<<grid, 256, SMEM_ATTN_BYTES>>>(qp, kp, vp, lm, ao);
    }

    // output projection
    split4_kernel<<<(NQ4 + 255) / 256, 256>>>(ao, aoh, aol, NQ4);
    {
        dim3 blk(256);
        dim3 go(ED / GBN, (BB * NQL) / GBM);
        gemm_mma<<<go, blk, GEMM_SMEM>>>(aoh, aol, wh + 3 * ED * ED, wl + 3 * ED * ED, wo_b, out);
    }
}

// round 7
// speedup vs baseline: 3.2290x; 1.9189x over previous
#include <cuda_runtime.h>
#include <cuda_bf16.h>
#include <math.h>
#include <stdint.h>

#define BB 4
#define NH 16
#define HD 64
#define ED 1024
#define NQL 1024
#define NKL 2048

// ---------------------------------------------------------------------------
// Scratch (no cudaMalloc allowed)
// ---------------------------------------------------------------------------
__device__ float g_logm[BB * NKL];        // log2 multiplicities

// bf16 split operands (inputs to projections)
__device__ __nv_bfloat16 g_xq_h[BB * NQL * ED], g_xq_l[BB * NQL * ED];
__device__ __nv_bfloat16 g_xk_h[BB * NKL * ED], g_xk_l[BB * NKL * ED];
__device__ __nv_bfloat16 g_xv_h[BB * NKL * ED], g_xv_l[BB * NKL * ED];
__device__ __nv_bfloat16 g_w_h[4 * ED * ED],    g_w_l[4 * ED * ED];

// projected split outputs
__device__ __nv_bfloat16 g_pq_h[BB * NQL * ED], g_pq_l[BB * NQL * ED];
__device__ __nv_bfloat16 g_pk_h[BB * NKL * ED], g_pk_l[BB * NKL * ED];
__device__ __nv_bfloat16 g_pv_h[BB * NKL * ED], g_pv_l[BB * NKL * ED];
__device__ __nv_bfloat16 g_ao_h[BB * NQL * ED], g_ao_l[BB * NQL * ED];

// single dynamic-smem symbol for the whole TU
extern __shared__ char dyn_smem[];

// ---------------------------------------------------------------------------
// helpers
// ---------------------------------------------------------------------------
__device__ __forceinline__ uint32_t smem_u32(const void* p) {
    uint32_t a;
    asm("{ .reg .u64 t; cvta.to.shared.u64 t, %1; cvt.u32.u64 %0, t; }"
        : "=r"(a) : "l"(p));
    return a;
}
__device__ __forceinline__ void cp16(uint32_t dst, const void* src) {
    asm volatile("cp.async.cg.shared.global [%0], [%1], 16;"
                 :: "r"(dst), "l"(src));
}
__device__ __forceinline__ void cp_commit() {
    asm volatile("cp.async.commit_group;");
}
__device__ __forceinline__ void cp_wait1() {
    asm volatile("cp.async.wait_group 1;" ::: "memory");
}
__device__ __forceinline__ void cp_wait0() {
    asm volatile("cp.async.wait_group 0;" ::: "memory");
}
__device__ __forceinline__ void ldsm4(uint32_t* r, uint32_t addr) {
    asm volatile("ldmatrix.sync.aligned.m8n8.x4.shared.b16 {%0,%1,%2,%3}, [%4];"
                 : "=r"(r[0]), "=r"(r[1]), "=r"(r[2]), "=r"(r[3]) : "r"(addr));
}
__device__ __forceinline__ void ldsm4t(uint32_t* r, uint32_t addr) {
    asm volatile("ldmatrix.sync.aligned.m8n8.x4.trans.shared.b16 {%0,%1,%2,%3}, [%4];"
                 : "=r"(r[0]), "=r"(r[1]), "=r"(r[2]), "=r"(r[3]) : "r"(addr));
}
__device__ __forceinline__ void mma16816(float* c, const uint32_t* a, const uint32_t* b) {
    asm volatile(
        "mma.sync.aligned.m16n8k16.row.col.f32.bf16.bf16.f32 "
        "{%0,%1,%2,%3}, {%4,%5,%6,%7}, {%8,%9}, {%0,%1,%2,%3};"
        : "+f"(c[0]), "+f"(c[1]), "+f"(c[2]), "+f"(c[3])
        : "r"(a[0]), "r"(a[1]), "r"(a[2]), "r"(a[3]), "r"(b[0]), "r"(b[1]));
}
// pack (lo, hi) floats -> bf16x2 (lo in low half)
__device__ __forceinline__ uint32_t packbf(float lo, float hi) {
    uint32_t r;
    asm("cvt.rn.bf16x2.f32 %0, %1, %2;" : "=r"(r) : "f"(hi), "f"(lo));
    return r;
}
// residual pack: (lo,hi) minus the bf16 values already packed in h
__device__ __forceinline__ uint32_t packlo(uint32_t h, float lo, float hi) {
    float hl = __int_as_float(h << 16);
    float hh = __int_as_float(h & 0xFFFF0000u);
    return packbf(lo - hl, hi - hh);
}
// fast 2^x on the FMA pipe (no MUFU). |err| ~ 2.4e-6 rel. x >= -126 clamped.
__device__ __forceinline__ float fexp2(float x) {
    x = fmaxf(x, -126.0f);
    float z = x + 12582912.0f;                 // round-to-nearest-int via magic
    int   n = __float_as_int(z) - 0x4B400000;
    float f = x - (z - 12582912.0f);           // f in [-0.5, 0.5]
    float p = 0.0013333558f;
    p = fmaf(p, f, 0.0096181291f);
    p = fmaf(p, f, 0.0555041087f);
    p = fmaf(p, f, 0.2402265070f);
    p = fmaf(p, f, 0.6931471806f);
    p = fmaf(p, f, 1.0f);
    return __int_as_float(__float_as_int(p) + (n << 23));
}

// ---------------------------------------------------------------------------
// split-bf16 HMMA GEMM:  C[M,1024] = A[M,1024] @ W[1024,1024]^T + bias
// mode 0: fp32 C.  mode 1: split bf16 (Chi, Clo) of (C+bias)*scale.
// ---------------------------------------------------------------------------
#define GBM 128
#define GBN 128
#define GBK 64
#define GNCH (ED / GBK)             // 16
#define TILE_B (GBM * GBK * 2)      // 16384 bytes
#define OFF_AH 0
#define OFF_AL (1 * TILE_B)
#define OFF_WH (2 * TILE_B)
#define OFF_WL (3 * TILE_B)
#define GBUF_B (4 * TILE_B)         // 65536
#define GEMM_SMEM (2 * GBUF_B)      // 131072

__device__ __forceinline__ void g_load_chunk(
    uint32_t buf, int tid, int bm, int bn, int k0,
    const __nv_bfloat16* __restrict__ Ah, const __nv_bfloat16* __restrict__ Al,
    const __nv_bfloat16* __restrict__ Wh, const __nv_bfloat16* __restrict__ Wl)
{
    #pragma unroll
    for (int i = 0; i < 4; i++) {
        int g   = tid + i * 256;        // 0..1023
        int row = g >> 3, kg = g & 7;
        uint32_t so = (uint32_t)(row * 128 + ((kg ^ (row & 7)) << 4));
        size_t ga = (size_t)(bm + row) * ED + k0 + kg * 8;
        size_t gw = (size_t)(bn + row) * ED + k0 + kg * 8;
        cp16(buf + OFF_AH + so, Ah + ga);
        cp16(buf + OFF_AL + so, Al + ga);
        cp16(buf + OFF_WH + so, Wh + gw);
        cp16(buf + OFF_WL + so, Wl + gw);
    }
    cp_commit();
}

__global__ __launch_bounds__(256, 1) void gemm_mma(
    const __nv_bfloat16* __restrict__ Ah, const __nv_bfloat16* __restrict__ Al,
    const __nv_bfloat16* __restrict__ Wh, const __nv_bfloat16* __restrict__ Wl,
    const float* __restrict__ bias, float* __restrict__ C,
    __nv_bfloat16* __restrict__ Chi, __nv_bfloat16* __restrict__ Clo,
    float scale, int mode)
{
    const uint32_t sb = smem_u32(dyn_smem);
    const int tid  = threadIdx.x;
    const int wid  = tid >> 5, lane = tid & 31;
    const int wm   = wid & 3, wn = wid >> 2;
    const int m0   = wm * 32, n0 = wn * 64;
    const int bm   = blockIdx.y * GBM;
    const int bn   = blockIdx.x * GBN;

    float acc[2][8][4];
    #pragma unroll
    for (int a = 0; a < 2; a++)
        #pragma unroll
        for (int b = 0; b < 8; b++)
            #pragma unroll
            for (int c = 0; c < 4; c++) acc[a][b][c] = 0.0f;

    const int rowA_in = (lane & 15);
    const int khA     = lane >> 4;
    const int nrow_in = ((lane & 16) >> 1) + (lane & 7);
    const int khB     = (lane >> 3) & 1;

    g_load_chunk(sb, tid, bm, bn, 0, Ah, Al, Wh, Wl);

    for (int ch = 0; ch < GNCH; ch++) {
        const uint32_t cur = sb + (uint32_t)(ch & 1) * GBUF_B;
        if (ch + 1 < GNCH) {
            g_load_chunk(sb + (uint32_t)((ch + 1) & 1) * GBUF_B, tid, bm, bn,
                         (ch + 1) * GBK, Ah, Al, Wh, Wl);
            cp_wait1();
        } else {
            cp_wait0();
        }
        __syncthreads();

        #pragma unroll
        for (int k16 = 0; k16 < 4; k16++) {
            uint32_t ah[2][4], al[2][4];
            const int kgA = k16 * 2 + khA;
            #pragma unroll
            for (int mt = 0; mt < 2; mt++) {
                int rA = m0 + mt * 16 + rowA_in;
                uint32_t off = (uint32_t)(rA * 128 + ((kgA ^ (rA & 7)) << 4));
                ldsm4(ah[mt], cur + OFF_AH + off);
                ldsm4(al[mt], cur + OFF_AL + off);
            }
            const int kgB = k16 * 2 + khB;
            #pragma unroll
            for (int g = 0; g < 4; g++) {
                int nr = n0 + g * 16 + nrow_in;
                uint32_t off = (uint32_t)(nr * 128 + ((kgB ^ (nr & 7)) << 4));
                uint32_t bh[4], bl[4];
                ldsm4(bh, cur + OFF_WH + off);
                ldsm4(bl, cur + OFF_WL + off);
                #pragma unroll
                for (int mt = 0; mt < 2; mt++) {
                    mma16816(acc[mt][g * 2 + 0], ah[mt], &bh[0]);
                    mma16816(acc[mt][g * 2 + 0], ah[mt], &bl[0]);
                    mma16816(acc[mt][g * 2 + 0], al[mt], &bh[0]);
                    mma16816(acc[mt][g * 2 + 1], ah[mt], &bh[2]);
                    mma16816(acc[mt][g * 2 + 1], ah[mt], &bl[2]);
                    mma16816(acc[mt][g * 2 + 1], al[mt], &bh[2]);
                }
            }
        }
        __syncthreads();
    }

    const int lr = lane >> 2;
    const int lc = (lane & 3) * 2;
    #pragma unroll
    for (int mt = 0; mt < 2; mt++) {
        #pragma unroll
        for (int nt = 0; nt < 8; nt++) {
            int row = bm + m0 + mt * 16 + lr;
            int col = bn + n0 + nt * 8 + lc;
            float2 b2 = *(const float2*)&bias[col];
            if (mode == 0) {
                float2 v0, v1;
                v0.x = acc[mt][nt][0] + b2.x;
                v0.y = acc[mt][nt][1] + b2.y;
                v1.x = acc[mt][nt][2] + b2.x;
                v1.y = acc[mt][nt][3] + b2.y;
                *(float2*)&C[(size_t)row * ED + col]       = v0;
                *(float2*)&C[(size_t)(row + 8) * ED + col] = v1;
            } else {
                float vx = (acc[mt][nt][0] + b2.x) * scale;
                float vy = (acc[mt][nt][1] + b2.y) * scale;
                uint32_t h0 = packbf(vx, vy);
                uint32_t l0 = packlo(h0, vx, vy);
                float wx = (acc[mt][nt][2] + b2.x) * scale;
                float wy = (acc[mt][nt][3] + b2.y) * scale;
                uint32_t h1 = packbf(wx, wy);
                uint32_t l1 = packlo(h1, wx, wy);
                *(uint32_t*)&Chi[(size_t)row * ED + col]       = h0;
                *(uint32_t*)&Clo[(size_t)row * ED + col]       = l0;
                *(uint32_t*)&Chi[(size_t)(row + 8) * ED + col] = h1;
                *(uint32_t*)&Clo[(size_t)(row + 8) * ED + col] = l1;
            }
        }
    }
}

// ---------------------------------------------------------------------------
// fp32 -> bf16 hi/lo split conversion
// ---------------------------------------------------------------------------
__global__ void split4_kernel(const float* __restrict__ x,
                              __nv_bfloat16* __restrict__ hi,
                              __nv_bfloat16* __restrict__ lo, int n4)
{
    int i = blockIdx.x * blockDim.x + threadIdx.x;
    if (i >= n4) return;
    float4 v = ((const float4*)x)[i];
    uint32_t h0 = packbf(v.x, v.y);
    uint32_t l0 = packlo(h0, v.x, v.y);
    uint32_t h1 = packbf(v.z, v.w);
    uint32_t l1 = packlo(h1, v.z, v.w);
    ((uint32_t*)hi)[2 * i]     = h0;
    ((uint32_t*)hi)[2 * i + 1] = h1;
    ((uint32_t*)lo)[2 * i]     = l0;
    ((uint32_t*)lo)[2 * i + 1] = l1;
}

__global__ void wsplit_kernel(const float* __restrict__ w0, const float* __restrict__ w1,
                              const float* __restrict__ w2, const float* __restrict__ w3,
                              __nv_bfloat16* __restrict__ hi,
                              __nv_bfloat16* __restrict__ lo)
{
    int i = blockIdx.x * blockDim.x + threadIdx.x;
    if (i >= 4 * ED * ED / 4) return;
    int which = i >> 18;
    int off = i & 262143;
    const float* w = which == 0 ? w0 : which == 1 ? w1 : which == 2 ? w2 : w3;
    float4 v = ((const float4*)w)[off];
    uint32_t h0 = packbf(v.x, v.y);
    uint32_t l0 = packlo(h0, v.x, v.y);
    uint32_t h1 = packbf(v.z, v.w);
    uint32_t l1 = packlo(h1, v.z, v.w);
    ((uint32_t*)hi)[2 * i]     = h0;
    ((uint32_t*)hi)[2 * i + 1] = h1;
    ((uint32_t*)lo)[2 * i]     = l0;
    ((uint32_t*)lo)[2 * i + 1] = l1;
}

// log2 of multiplicities
__global__ void logm_kernel(const float* __restrict__ m, float* __restrict__ lm, int n)
{
    int i = blockIdx.x * blockDim.x + threadIdx.x;
    if (i < n) lm[i] = log2f(m[i]);
}

// ---------------------------------------------------------------------------
// HMMA flash attention (no-max softmax in log2 domain).
// Block = (q-tile 128, head, batch); 8 warps, warp = 16 q-rows x full width.
// Q pre-scaled by log2(e)/8 at projection. logits2 = S + log2(m).
// ---------------------------------------------------------------------------
#define AT_QH 0
#define AT_QL 16384
#define AT_BUF0 32768
#define AT_KH 0
#define AT_KL 16384
#define AT_VH 32768
#define AT_VL 49152
#define AT_LM 65536
#define AT_BUFB 66048                 // per double-buffer stride
#define ATTN_SMEM (AT_BUF0 + 2 * AT_BUFB)   // 164864

__device__ __forceinline__ void attn_load_tile(
    uint32_t buf, int tid, int b, int h, int k0,
    const __nv_bfloat16* __restrict__ Kh, const __nv_bfloat16* __restrict__ Kl,
    const __nv_bfloat16* __restrict__ Vh, const __nv_bfloat16* __restrict__ Vl,
    const float* __restrict__ lm)
{
    #pragma unroll
    for (int i = 0; i < 4; i++) {
        int g   = tid + i * 256;        // 0..1023
        int row = g >> 3, kg = g & 7;
        uint32_t so = (uint32_t)(row * 128 + ((kg ^ (row & 7)) << 4));
        size_t gk = (size_t)(b * NKL + k0 + row) * ED + h * HD + kg * 8;
        cp16(buf + AT_KH + so, Kh + gk);
        cp16(buf + AT_KL + so, Kl + gk);
        cp16(buf + AT_VH + so, Vh + gk);
        cp16(buf + AT_VL + so, Vl + gk);
    }
    if (tid < 32)
        cp16(buf + AT_LM + tid * 16, lm + b * NKL + k0 + tid * 4);
    cp_commit();
}

__global__ __launch_bounds__(256, 1) void attn_mma(
    const __nv_bfloat16* __restrict__ Qh, const __nv_bfloat16* __restrict__ Ql,
    const __nv_bfloat16* __restrict__ Kh, const __nv_bfloat16* __restrict__ Kl,
    const __nv_bfloat16* __restrict__ Vh, const __nv_bfloat16* __restrict__ Vl,
    const float* __restrict__ logm,
    __nv_bfloat16* __restrict__ Ohi, __nv_bfloat16* __restrict__ Olo)
{
    const uint32_t sb = smem_u32(dyn_smem);
    const int tid  = threadIdx.x;
    const int wid  = tid >> 5, lane = tid & 31;
    const int qt = blockIdx.x, h = blockIdx.y, b = blockIdx.z;
    const int q0 = qt * 128;
    const int m0 = wid * 16;

    const int rowA_in = (lane & 15);
    const int khA     = lane >> 4;
    const int nrow_in = ((lane & 16) >> 1) + (lane & 7);
    const int khB     = (lane >> 3) & 1;

    // Q tile load (q-rows 0..127, 64 d) hi/lo
    #pragma unroll
    for (int i = 0; i < 4; i++) {
        int g   = tid + i * 256;
        int row = g >> 3, kg = g & 7;
        uint32_t so = (uint32_t)(row * 128 + ((kg ^ (row & 7)) << 4));
        size_t gq = (size_t)(b * NQL + q0 + row) * ED + h * HD + kg * 8;
        cp16(sb + AT_QH + so, Qh + gq);
        cp16(sb + AT_QL + so, Ql + gq);
    }
    cp_commit();
    attn_load_tile(sb + AT_BUF0, tid, b, h, 0, Kh, Kl, Vh, Vl, logm);
    // (two groups pending; drain both before first compute)

    float oacc[8][4];
    #pragma unroll
    for (int j = 0; j < 8; j++)
        #pragma unroll
        for (int c = 0; c < 4; c++) oacc[j][c] = 0.0f;
    float lsum0 = 0.0f, lsum1 = 0.0f;

    const int NT = NKL / 128;   // 16
    for (int t = 0; t < NT; t++) {
        const uint32_t cur = sb + AT_BUF0 + (uint32_t)(t & 1) * AT_BUFB;
        if (t + 1 < NT) {
            attn_load_tile(sb + AT_BUF0 + (uint32_t)((t + 1) & 1) * AT_BUFB,
                           tid, b, h, (t + 1) * 128, Kh, Kl, Vh, Vl, logm);
            cp_wait1();
        } else {
            cp_wait0();
        }
        __syncthreads();

        // ---- S = Q K^T (split, 3 terms), warp rows m0..m0+15, cols 0..127
        float s[16][4];
        #pragma unroll
        for (int j = 0; j < 16; j++)
            #pragma unroll
            for (int c = 0; c < 4; c++) s[j][c] = 0.0f;

        #pragma unroll
        for (int k16 = 0; k16 < 4; k16++) {
            uint32_t qah[4], qal[4];
            const int kgA = k16 * 2 + khA;
            {
                int rA = m0 + rowA_in;
                uint32_t off = (uint32_t)(rA * 128 + ((kgA ^ (rA & 7)) << 4));
                ldsm4(qah, sb + AT_QH + off);
                ldsm4(qal, sb + AT_QL + off);
            }
            const int kgB = k16 * 2 + khB;
            #pragma unroll
            for (int g = 0; g < 8; g++) {
                int nr = g * 16 + nrow_in;
                uint32_t off = (uint32_t)(nr * 128 + ((kgB ^ (nr & 7)) << 4));
                uint32_t bh[4], bl[4];
                ldsm4(bh, cur + AT_KH + off);
                ldsm4(bl, cur + AT_KL + off);
                mma16816(s[g * 2 + 0], qah, &bh[0]);
                mma16816(s[g * 2 + 0], qah, &bl[0]);
                mma16816(s[g * 2 + 0], qal, &bh[0]);
                mma16816(s[g * 2 + 1], qah, &bh[2]);
                mma16816(s[g * 2 + 1], qah, &bl[2]);
                mma16816(s[g * 2 + 1], qal, &bh[2]);
            }
        }

        // ---- softmax numerator: p = 2^(s + log2 m), accumulate row sums
        const float* LmS = (const float*)(dyn_smem +
            (AT_BUF0 + (size_t)(t & 1) * AT_BUFB + AT_LM));
        #pragma unroll
        for (int j = 0; j < 16; j++) {
            float2 l2 = *(const float2*)&LmS[8 * j + (lane & 3) * 2];
            s[j][0] = fexp2(s[j][0] + l2.x);
            s[j][1] = fexp2(s[j][1] + l2.y);
            s[j][2] = fexp2(s[j][2] + l2.x);
            s[j][3] = fexp2(s[j][3] + l2.y);
            lsum0 += s[j][0] + s[j][1];
            lsum1 += s[j][2] + s[j][3];
        }

        // ---- O += P V (split, 3 terms). P fragments built from s in-register.
        #pragma unroll
        for (int kt = 0; kt < 8; kt++) {
            uint32_t aph[4], apl[4];
            aph[0] = packbf(s[2 * kt][0],     s[2 * kt][1]);
            apl[0] = packlo(aph[0], s[2 * kt][0], s[2 * kt][1]);
            aph[1] = packbf(s[2 * kt][2],     s[2 * kt][3]);
            apl[1] = packlo(aph[1], s[2 * kt][2], s[2 * kt][3]);
            aph[2] = packbf(s[2 * kt + 1][0], s[2 * kt + 1][1]);
            apl[2] = packlo(aph[2], s[2 * kt + 1][0], s[2 * kt + 1][1]);
            aph[3] = packbf(s[2 * kt + 1][2], s[2 * kt + 1][3]);
            apl[3] = packlo(aph[3], s[2 * kt + 1][2], s[2 * kt + 1][3]);

            #pragma unroll
            for (int j = 0; j < 4; j++) {   // d-chunk pairs (16 d per iter)
                int row = kt * 16 + (lane & 15);
                int ck  = 2 * j + (lane >> 4);
                uint32_t off = (uint32_t)(row * 128 + ((ck ^ (row & 7)) << 4));
                uint32_t vhf[4], vlf[4];
                ldsm4t(vhf, cur + AT_VH + off);
                ldsm4t(vlf, cur + AT_VL + off);
                mma16816(oacc[2 * j + 0], aph, &vhf[0]);
                mma16816(oacc[2 * j + 0], aph, &vlf[0]);
                mma16816(oacc[2 * j + 0], apl, &vhf[0]);
                mma16816(oacc[2 * j + 1], aph, &vhf[2]);
                mma16816(oacc[2 * j + 1], aph, &vlf[2]);
                mma16816(oacc[2 * j + 1], apl, &vhf[2]);
            }
        }
        __syncthreads();
    }

    // ---- reduce row sums over the 4 lanes of each row quad
    #pragma unroll
    for (int off = 1; off <= 2; off <<= 1) {
        lsum0 += __shfl_xor_sync(0xffffffffu, lsum0, off);
        lsum1 += __shfl_xor_sync(0xffffffffu, lsum1, off);
    }
    const float inv0 = 1.0f / lsum0;
    const float inv1 = 1.0f / lsum1;

    // ---- normalize + split bf16 write to [b, q, h*64 + d]
    const int row0 = q0 + m0 + (lane >> 2);
    const int col0 = h * HD + (lane & 3) * 2;
    #pragma unroll
    for (int j = 0; j < 8; j++) {
        int col = col0 + 8 * j;
        float vx = oacc[j][0] * inv0, vy = oacc[j][1] * inv0;
        uint32_t h0 = packbf(vx, vy);
        uint32_t l0 = packlo(h0, vx, vy);
        float wx = oacc[j][2] * inv1, wy = oacc[j][3] * inv1;
        uint32_t h1 = packbf(wx, wy);
        uint32_t l1 = packlo(h1, wx, wy);
        *(uint32_t*)&Ohi[(size_t)(b * NQL + row0) * ED + col]     = h0;
        *(uint32_t*)&Olo[(size_t)(b * NQL + row0) * ED + col]     = l0;
        *(uint32_t*)&Ohi[(size_t)(b * NQL + row0 + 8) * ED + col] = h1;
        *(uint32_t*)&Olo[(size_t)(b * NQL + row0 + 8) * ED + col] = l1;
    }
}

// ---------------------------------------------------------------------------
extern "C" void kernel_launch(void* const* d_in, const int* in_sizes, int n_in,
                              void* d_out, int out_size)
{
    const float* query = (const float*)d_in[0];
    const float* key   = (const float*)d_in[1];
    const float* value = (const float*)d_in[2];
    const float* kmult = (const float*)d_in[3];
    const float* wq_w  = (const float*)d_in[4];
    const float* wq_b  = (const float*)d_in[5];
    const float* wk_w  = (const float*)d_in[6];
    const float* wk_b  = (const float*)d_in[7];
    const float* wv_w  = (const float*)d_in[8];
    const float* wv_b  = (const float*)d_in[9];
    const float* wo_w  = (const float*)d_in[10];
    const float* wo_b  = (const float*)d_in[11];
    float* out = (float*)d_out;

    float* lm;
    cudaGetSymbolAddress((void**)&lm, g_logm);
    __nv_bfloat16 *xqh, *xql, *xkh, *xkl, *xvh, *xvl, *wh, *wl;
    __nv_bfloat16 *pqh, *pql, *pkh, *pkl, *pvh, *pvl, *aoh, *aol;
    cudaGetSymbolAddress((void**)&xqh, g_xq_h);
    cudaGetSymbolAddress((void**)&xql, g_xq_l);
    cudaGetSymbolAddress((void**)&xkh, g_xk_h);
    cudaGetSymbolAddress((void**)&xkl, g_xk_l);
    cudaGetSymbolAddress((void**)&xvh, g_xv_h);
    cudaGetSymbolAddress((void**)&xvl, g_xv_l);
    cudaGetSymbolAddress((void**)&wh,  g_w_h);
    cudaGetSymbolAddress((void**)&wl,  g_w_l);
    cudaGetSymbolAddress((void**)&pqh, g_pq_h);
    cudaGetSymbolAddress((void**)&pql, g_pq_l);
    cudaGetSymbolAddress((void**)&pkh, g_pk_h);
    cudaGetSymbolAddress((void**)&pkl, g_pk_l);
    cudaGetSymbolAddress((void**)&pvh, g_pv_h);
    cudaGetSymbolAddress((void**)&pvl, g_pv_l);
    cudaGetSymbolAddress((void**)&aoh, g_ao_h);
    cudaGetSymbolAddress((void**)&aol, g_ao_l);

    cudaFuncSetAttribute(gemm_mma,
                         cudaFuncAttributeMaxDynamicSharedMemorySize, GEMM_SMEM);
    cudaFuncSetAttribute(attn_mma,
                         cudaFuncAttributeMaxDynamicSharedMemorySize, ATTN_SMEM);

    const int NQ4 = BB * NQL * ED / 4;
    const int NK4 = BB * NKL * ED / 4;
    const float QSCALE = 0.18033688011112042f;   // log2(e)/8

    // input hi/lo conversions + log2(multiplicities)
    split4_kernel<<<(NQ4 + 255) / 256, 256>>>(query, xqh, xql, NQ4);
    split4_kernel<<<(NK4 + 255) / 256, 256>>>(key,   xkh, xkl, NK4);
    split4_kernel<<<(NK4 + 255) / 256, 256>>>(value, xvh, xvl, NK4);
    wsplit_kernel<<<(4 * ED * ED / 4 + 255) / 256, 256>>>(wq_w, wk_w, wv_w, wo_w, wh, wl);
    logm_kernel<<<(BB * NKL + 255) / 256, 256>>>(kmult, lm, BB * NKL);

    // Q/K/V projections -> split bf16 outputs (Q pre-scaled by log2e/8)
    {
        dim3 blk(256);
        dim3 gq(ED / GBN, (BB * NQL) / GBM);   // (8, 32)
        dim3 gk(ED / GBN, (BB * NKL) / GBM);   // (8, 64)
        gemm_mma<<<gq, blk, GEMM_SMEM>>>(xqh, xql, wh + 0 * ED * ED, wl + 0 * ED * ED,
                                         wq_b, nullptr, pqh, pql, QSCALE, 1);
        gemm_mma<<<gk, blk, GEMM_SMEM>>>(xkh, xkl, wh + 1 * ED * ED, wl + 1 * ED * ED,
                                         wk_b, nullptr, pkh, pkl, 1.0f, 1);
        gemm_mma<<<gk, blk, GEMM_SMEM>>>(xvh, xvl, wh + 2 * ED * ED, wl + 2 * ED * ED,
                                         wv_b, nullptr, pvh, pvl, 1.0f, 1);
    }

    // attention (HMMA, split bf16 in/out)
    {
        dim3 grid(NQL / 128, NH, BB);
        attn_mma<<<grid, 256, ATTN_SMEM>>>(pqh, pql, pkh, pkl, pvh, pvl, lm, aoh, aol);
    }

    // output projection (fp32 out)
    {
        dim3 blk(256);
        dim3 go(ED / GBN, (BB * NQL) / GBM);
        gemm_mma<<<go, blk, GEMM_SMEM>>>(aoh, aol, wh + 3 * ED * ED, wl + 3 * ED * ED,
                                         wo_b, out, nullptr, nullptr, 1.0f, 0);
    }
}

// round 8
// speedup vs baseline: 3.6947x; 1.1442x over previous
#include <cuda_runtime.h>
#include <cuda_bf16.h>
#include <cuda_fp16.h>
#include <math.h>
#include <stdint.h>

#define BB 4
#define NH 16
#define HD 64
#define ED 1024
#define NQL 1024
#define NKL 2048

// ---------------------------------------------------------------------------
// Scratch (no cudaMalloc allowed)
// ---------------------------------------------------------------------------
__device__ float g_logm[BB * NKL];        // log2 multiplicities

// bf16 split operands (inputs to projections)
__device__ __nv_bfloat16 g_xq_h[BB * NQL * ED], g_xq_l[BB * NQL * ED];
__device__ __nv_bfloat16 g_xk_h[BB * NKL * ED], g_xk_l[BB * NKL * ED];
__device__ __nv_bfloat16 g_xv_h[BB * NKL * ED], g_xv_l[BB * NKL * ED];
__device__ __nv_bfloat16 g_w_h[3 * ED * ED],    g_w_l[3 * ED * ED];   // wq, wk, wv
__device__ __half        g_wo16h[ED * ED],      g_wo16l[ED * ED];     // wo fp16 split

// projected outputs
__device__ __nv_bfloat16 g_pq_h[BB * NQL * ED], g_pq_l[BB * NQL * ED];
__device__ __nv_bfloat16 g_pk_h[BB * NKL * ED], g_pk_l[BB * NKL * ED];
__device__ __half        g_pv16[BB * NKL * ED];     // V fp16 single
__device__ __half        g_ao16[BB * NQL * ED];     // attention out fp16 single

// single dynamic-smem symbol for the whole TU
extern __shared__ char dyn_smem[];

// ---------------------------------------------------------------------------
// helpers
// ---------------------------------------------------------------------------
__device__ __forceinline__ uint32_t smem_u32(const void* p) {
    uint32_t a;
    asm("{ .reg .u64 t; cvta.to.shared.u64 t, %1; cvt.u32.u64 %0, t; }"
        : "=r"(a) : "l"(p));
    return a;
}
__device__ __forceinline__ void cp16(uint32_t dst, const void* src) {
    asm volatile("cp.async.cg.shared.global [%0], [%1], 16;"
                 :: "r"(dst), "l"(src));
}
__device__ __forceinline__ void cp_commit() {
    asm volatile("cp.async.commit_group;");
}
__device__ __forceinline__ void cp_wait1() {
    asm volatile("cp.async.wait_group 1;" ::: "memory");
}
__device__ __forceinline__ void cp_wait0() {
    asm volatile("cp.async.wait_group 0;" ::: "memory");
}
__device__ __forceinline__ void ldsm4(uint32_t* r, uint32_t addr) {
    asm volatile("ldmatrix.sync.aligned.m8n8.x4.shared.b16 {%0,%1,%2,%3}, [%4];"
                 : "=r"(r[0]), "=r"(r[1]), "=r"(r[2]), "=r"(r[3]) : "r"(addr));
}
__device__ __forceinline__ void ldsm4t(uint32_t* r, uint32_t addr) {
    asm volatile("ldmatrix.sync.aligned.m8n8.x4.trans.shared.b16 {%0,%1,%2,%3}, [%4];"
                 : "=r"(r[0]), "=r"(r[1]), "=r"(r[2]), "=r"(r[3]) : "r"(addr));
}
__device__ __forceinline__ void mma16816(float* c, const uint32_t* a, const uint32_t* b) {
    asm volatile(
        "mma.sync.aligned.m16n8k16.row.col.f32.bf16.bf16.f32 "
        "{%0,%1,%2,%3}, {%4,%5,%6,%7}, {%8,%9}, {%0,%1,%2,%3};"
        : "+f"(c[0]), "+f"(c[1]), "+f"(c[2]), "+f"(c[3])
        : "r"(a[0]), "r"(a[1]), "r"(a[2]), "r"(a[3]), "r"(b[0]), "r"(b[1]));
}
__device__ __forceinline__ void mma16816h(float* c, const uint32_t* a, const uint32_t* b) {
    asm volatile(
        "mma.sync.aligned.m16n8k16.row.col.f32.f16.f16.f32 "
        "{%0,%1,%2,%3}, {%4,%5,%6,%7}, {%8,%9}, {%0,%1,%2,%3};"
        : "+f"(c[0]), "+f"(c[1]), "+f"(c[2]), "+f"(c[3])
        : "r"(a[0]), "r"(a[1]), "r"(a[2]), "r"(a[3]), "r"(b[0]), "r"(b[1]));
}
// pack (lo, hi) floats -> bf16x2 (lo in low half)
__device__ __forceinline__ uint32_t packbf(float lo, float hi) {
    uint32_t r;
    asm("cvt.rn.bf16x2.f32 %0, %1, %2;" : "=r"(r) : "f"(hi), "f"(lo));
    return r;
}
// residual pack: (lo,hi) minus the bf16 values already packed in h
__device__ __forceinline__ uint32_t packlo(uint32_t h, float lo, float hi) {
    float hl = __int_as_float(h << 16);
    float hh = __int_as_float(h & 0xFFFF0000u);
    return packbf(lo - hl, hi - hh);
}
// pack (lo, hi) floats -> f16x2 (lo in low half)
__device__ __forceinline__ uint32_t packhf(float lo, float hi) {
    uint32_t r;
    asm("cvt.rn.f16x2.f32 %0, %1, %2;" : "=r"(r) : "f"(hi), "f"(lo));
    return r;
}
// fast 2^x on the FMA pipe (no MUFU). |err| ~ 2.4e-6 rel. x >= -126 clamped.
__device__ __forceinline__ float fexp2(float x) {
    x = fmaxf(x, -126.0f);
    float z = x + 12582912.0f;                 // round-to-nearest-int via magic
    int   n = __float_as_int(z) - 0x4B400000;
    float f = x - (z - 12582912.0f);           // f in [-0.5, 0.5]
    float p = 0.0013333558f;
    p = fmaf(p, f, 0.0096181291f);
    p = fmaf(p, f, 0.0555041087f);
    p = fmaf(p, f, 0.2402265070f);
    p = fmaf(p, f, 0.6931471806f);
    p = fmaf(p, f, 1.0f);
    return __int_as_float(__float_as_int(p) + (n << 23));
}

// ---------------------------------------------------------------------------
// split-bf16 HMMA GEMM:  C[M,1024] = A[M,1024] @ W[1024,1024]^T + bias
// mode 1: split bf16 (Chi, Clo) of (C+bias)*scale.   mode 2: fp16 single C16.
// ---------------------------------------------------------------------------
#define GBM 128
#define GBN 128
#define GBK 64
#define GNCH (ED / GBK)             // 16
#define TILE_B (GBM * GBK * 2)      // 16384 bytes
#define OFF_AH 0
#define OFF_AL (1 * TILE_B)
#define OFF_WH (2 * TILE_B)
#define OFF_WL (3 * TILE_B)
#define GBUF_B (4 * TILE_B)         // 65536
#define GEMM_SMEM (2 * GBUF_B)      // 131072

__device__ __forceinline__ void g_load_chunk(
    uint32_t buf, int tid, int bm, int bn, int k0,
    const __nv_bfloat16* __restrict__ Ah, const __nv_bfloat16* __restrict__ Al,
    const __nv_bfloat16* __restrict__ Wh, const __nv_bfloat16* __restrict__ Wl)
{
    #pragma unroll
    for (int i = 0; i < 4; i++) {
        int g   = tid + i * 256;        // 0..1023
        int row = g >> 3, kg = g & 7;
        uint32_t so = (uint32_t)(row * 128 + ((kg ^ (row & 7)) << 4));
        size_t ga = (size_t)(bm + row) * ED + k0 + kg * 8;
        size_t gw = (size_t)(bn + row) * ED + k0 + kg * 8;
        cp16(buf + OFF_AH + so, Ah + ga);
        cp16(buf + OFF_AL + so, Al + ga);
        cp16(buf + OFF_WH + so, Wh + gw);
        cp16(buf + OFF_WL + so, Wl + gw);
    }
    cp_commit();
}

__global__ __launch_bounds__(256, 1) void gemm_mma(
    const __nv_bfloat16* __restrict__ Ah, const __nv_bfloat16* __restrict__ Al,
    const __nv_bfloat16* __restrict__ Wh, const __nv_bfloat16* __restrict__ Wl,
    const float* __restrict__ bias,
    __nv_bfloat16* __restrict__ Chi, __nv_bfloat16* __restrict__ Clo,
    __half* __restrict__ C16,
    float scale, int mode)
{
    const uint32_t sb = smem_u32(dyn_smem);
    const int tid  = threadIdx.x;
    const int wid  = tid >> 5, lane = tid & 31;
    const int wm   = wid & 3, wn = wid >> 2;
    const int m0   = wm * 32, n0 = wn * 64;
    const int bm   = blockIdx.y * GBM;
    const int bn   = blockIdx.x * GBN;

    float acc[2][8][4];
    #pragma unroll
    for (int a = 0; a < 2; a++)
        #pragma unroll
        for (int b = 0; b < 8; b++)
            #pragma unroll
            for (int c = 0; c < 4; c++) acc[a][b][c] = 0.0f;

    const int rowA_in = (lane & 15);
    const int khA     = lane >> 4;
    const int nrow_in = ((lane & 16) >> 1) + (lane & 7);
    const int khB     = (lane >> 3) & 1;

    g_load_chunk(sb, tid, bm, bn, 0, Ah, Al, Wh, Wl);

    for (int ch = 0; ch < GNCH; ch++) {
        const uint32_t cur = sb + (uint32_t)(ch & 1) * GBUF_B;
        if (ch + 1 < GNCH) {
            g_load_chunk(sb + (uint32_t)((ch + 1) & 1) * GBUF_B, tid, bm, bn,
                         (ch + 1) * GBK, Ah, Al, Wh, Wl);
            cp_wait1();
        } else {
            cp_wait0();
        }
        __syncthreads();

        #pragma unroll
        for (int k16 = 0; k16 < 4; k16++) {
            uint32_t ah[2][4], al[2][4];
            const int kgA = k16 * 2 + khA;
            #pragma unroll
            for (int mt = 0; mt < 2; mt++) {
                int rA = m0 + mt * 16 + rowA_in;
                uint32_t off = (uint32_t)(rA * 128 + ((kgA ^ (rA & 7)) << 4));
                ldsm4(ah[mt], cur + OFF_AH + off);
                ldsm4(al[mt], cur + OFF_AL + off);
            }
            const int kgB = k16 * 2 + khB;
            #pragma unroll
            for (int g = 0; g < 4; g++) {
                int nr = n0 + g * 16 + nrow_in;
                uint32_t off = (uint32_t)(nr * 128 + ((kgB ^ (nr & 7)) << 4));
                uint32_t bh[4], bl[4];
                ldsm4(bh, cur + OFF_WH + off);
                ldsm4(bl, cur + OFF_WL + off);
                #pragma unroll
                for (int mt = 0; mt < 2; mt++) {
                    mma16816(acc[mt][g * 2 + 0], ah[mt], &bh[0]);
                    mma16816(acc[mt][g * 2 + 0], ah[mt], &bl[0]);
                    mma16816(acc[mt][g * 2 + 0], al[mt], &bh[0]);
                    mma16816(acc[mt][g * 2 + 1], ah[mt], &bh[2]);
                    mma16816(acc[mt][g * 2 + 1], ah[mt], &bl[2]);
                    mma16816(acc[mt][g * 2 + 1], al[mt], &bh[2]);
                }
            }
        }
        __syncthreads();
    }

    const int lr = lane >> 2;
    const int lc = (lane & 3) * 2;
    #pragma unroll
    for (int mt = 0; mt < 2; mt++) {
        #pragma unroll
        for (int nt = 0; nt < 8; nt++) {
            int row = bm + m0 + mt * 16 + lr;
            int col = bn + n0 + nt * 8 + lc;
            float2 b2 = *(const float2*)&bias[col];
            float vx = (acc[mt][nt][0] + b2.x) * scale;
            float vy = (acc[mt][nt][1] + b2.y) * scale;
            float wx = (acc[mt][nt][2] + b2.x) * scale;
            float wy = (acc[mt][nt][3] + b2.y) * scale;
            if (mode == 1) {
                uint32_t h0 = packbf(vx, vy);
                uint32_t l0 = packlo(h0, vx, vy);
                uint32_t h1 = packbf(wx, wy);
                uint32_t l1 = packlo(h1, wx, wy);
                *(uint32_t*)&Chi[(size_t)row * ED + col]       = h0;
                *(uint32_t*)&Clo[(size_t)row * ED + col]       = l0;
                *(uint32_t*)&Chi[(size_t)(row + 8) * ED + col] = h1;
                *(uint32_t*)&Clo[(size_t)(row + 8) * ED + col] = l1;
            } else {
                *(uint32_t*)&C16[(size_t)row * ED + col]       = packhf(vx, vy);
                *(uint32_t*)&C16[(size_t)(row + 8) * ED + col] = packhf(wx, wy);
            }
        }
    }
}

// ---------------------------------------------------------------------------
// O-projection GEMM: A fp16 single x W fp16 2-term split -> fp32 out + bias
// ---------------------------------------------------------------------------
#define GO_A 0
#define GO_WH TILE_B
#define GO_WL (2 * TILE_B)
#define GO_BUF (3 * TILE_B)          // 49152
#define GEMMO_SMEM (2 * GO_BUF)      // 98304

__device__ __forceinline__ void o_load_chunk(
    uint32_t buf, int tid, int bm, int bn, int k0,
    const __half* __restrict__ A,
    const __half* __restrict__ Wh, const __half* __restrict__ Wl)
{
    #pragma unroll
    for (int i = 0; i < 4; i++) {
        int g   = tid + i * 256;
        int row = g >> 3, kg = g & 7;
        uint32_t so = (uint32_t)(row * 128 + ((kg ^ (row & 7)) << 4));
        size_t ga = (size_t)(bm + row) * ED + k0 + kg * 8;
        size_t gw = (size_t)(bn + row) * ED + k0 + kg * 8;
        cp16(buf + GO_A + so, A + ga);
        cp16(buf + GO_WH + so, Wh + gw);
        cp16(buf + GO_WL + so, Wl + gw);
    }
    cp_commit();
}

__global__ __launch_bounds__(256, 1) void gemm_o(
    const __half* __restrict__ A,
    const __half* __restrict__ Wh, const __half* __restrict__ Wl,
    const float* __restrict__ bias, float* __restrict__ C)
{
    const uint32_t sb = smem_u32(dyn_smem);
    const int tid  = threadIdx.x;
    const int wid  = tid >> 5, lane = tid & 31;
    const int wm   = wid & 3, wn = wid >> 2;
    const int m0   = wm * 32, n0 = wn * 64;
    const int bm   = blockIdx.y * GBM;
    const int bn   = blockIdx.x * GBN;

    float acc[2][8][4];
    #pragma unroll
    for (int a = 0; a < 2; a++)
        #pragma unroll
        for (int b = 0; b < 8; b++)
            #pragma unroll
            for (int c = 0; c < 4; c++) acc[a][b][c] = 0.0f;

    const int rowA_in = (lane & 15);
    const int khA     = lane >> 4;
    const int nrow_in = ((lane & 16) >> 1) + (lane & 7);
    const int khB     = (lane >> 3) & 1;

    o_load_chunk(sb, tid, bm, bn, 0, A, Wh, Wl);

    for (int ch = 0; ch < GNCH; ch++) {
        const uint32_t cur = sb + (uint32_t)(ch & 1) * GO_BUF;
        if (ch + 1 < GNCH) {
            o_load_chunk(sb + (uint32_t)((ch + 1) & 1) * GO_BUF, tid, bm, bn,
                         (ch + 1) * GBK, A, Wh, Wl);
            cp_wait1();
        } else {
            cp_wait0();
        }
        __syncthreads();

        #pragma unroll
        for (int k16 = 0; k16 < 4; k16++) {
            uint32_t ah[2][4];
            const int kgA = k16 * 2 + khA;
            #pragma unroll
            for (int mt = 0; mt < 2; mt++) {
                int rA = m0 + mt * 16 + rowA_in;
                uint32_t off = (uint32_t)(rA * 128 + ((kgA ^ (rA & 7)) << 4));
                ldsm4(ah[mt], cur + GO_A + off);
            }
            const int kgB = k16 * 2 + khB;
            #pragma unroll
            for (int g = 0; g < 4; g++) {
                int nr = n0 + g * 16 + nrow_in;
                uint32_t off = (uint32_t)(nr * 128 + ((kgB ^ (nr & 7)) << 4));
                uint32_t bh[4], bl[4];
                ldsm4(bh, cur + GO_WH + off);
                ldsm4(bl, cur + GO_WL + off);
                #pragma unroll
                for (int mt = 0; mt < 2; mt++) {
                    mma16816h(acc[mt][g * 2 + 0], ah[mt], &bh[0]);
                    mma16816h(acc[mt][g * 2 + 0], ah[mt], &bl[0]);
                    mma16816h(acc[mt][g * 2 + 1], ah[mt], &bh[2]);
                    mma16816h(acc[mt][g * 2 + 1], ah[mt], &bl[2]);
                }
            }
        }
        __syncthreads();
    }

    const int lr = lane >> 2;
    const int lc = (lane & 3) * 2;
    #pragma unroll
    for (int mt = 0; mt < 2; mt++) {
        #pragma unroll
        for (int nt = 0; nt < 8; nt++) {
            int row = bm + m0 + mt * 16 + lr;
            int col = bn + n0 + nt * 8 + lc;
            float2 b2 = *(const float2*)&bias[col];
            float2 v0, v1;
            v0.x = acc[mt][nt][0] + b2.x;
            v0.y = acc[mt][nt][1] + b2.y;
            v1.x = acc[mt][nt][2] + b2.x;
            v1.y = acc[mt][nt][3] + b2.y;
            *(float2*)&C[(size_t)row * ED + col]       = v0;
            *(float2*)&C[(size_t)(row + 8) * ED + col] = v1;
        }
    }
}

// ---------------------------------------------------------------------------
// conversions
// ---------------------------------------------------------------------------
__global__ void split4_kernel(const float* __restrict__ x,
                              __nv_bfloat16* __restrict__ hi,
                              __nv_bfloat16* __restrict__ lo, int n4)
{
    int i = blockIdx.x * blockDim.x + threadIdx.x;
    if (i >= n4) return;
    float4 v = ((const float4*)x)[i];
    uint32_t h0 = packbf(v.x, v.y);
    uint32_t l0 = packlo(h0, v.x, v.y);
    uint32_t h1 = packbf(v.z, v.w);
    uint32_t l1 = packlo(h1, v.z, v.w);
    ((uint32_t*)hi)[2 * i]     = h0;
    ((uint32_t*)hi)[2 * i + 1] = h1;
    ((uint32_t*)lo)[2 * i]     = l0;
    ((uint32_t*)lo)[2 * i + 1] = l1;
}

__global__ void wsplit_kernel(const float* __restrict__ w0, const float* __restrict__ w1,
                              const float* __restrict__ w2,
                              __nv_bfloat16* __restrict__ hi,
                              __nv_bfloat16* __restrict__ lo)
{
    int i = blockIdx.x * blockDim.x + threadIdx.x;
    if (i >= 3 * ED * ED / 4) return;
    int which = i >> 18;
    int off = i & 262143;
    const float* w = which == 0 ? w0 : which == 1 ? w1 : w2;
    float4 v = ((const float4*)w)[off];
    uint32_t h0 = packbf(v.x, v.y);
    uint32_t l0 = packlo(h0, v.x, v.y);
    uint32_t h1 = packbf(v.z, v.w);
    uint32_t l1 = packlo(h1, v.z, v.w);
    ((uint32_t*)hi)[2 * i]     = h0;
    ((uint32_t*)hi)[2 * i + 1] = h1;
    ((uint32_t*)lo)[2 * i]     = l0;
    ((uint32_t*)lo)[2 * i + 1] = l1;
}

// wo -> fp16 hi/lo split
__global__ void wsplit16_kernel(const float* __restrict__ w,
                                __half* __restrict__ hi, __half* __restrict__ lo)
{
    int i = blockIdx.x * blockDim.x + threadIdx.x;
    if (i >= ED * ED / 4) return;
    float4 v = ((const float4*)w)[i];
    __half h0 = __float2half(v.x), h1 = __float2half(v.y);
    __half h2 = __float2half(v.z), h3 = __float2half(v.w);
    __half l0 = __float2half(v.x - __half2float(h0));
    __half l1 = __float2half(v.y - __half2float(h1));
    __half l2 = __float2half(v.z - __half2float(h2));
    __half l3 = __float2half(v.w - __half2float(h3));
    ((__half2*)hi)[2 * i]     = __halves2half2(h0, h1);
    ((__half2*)hi)[2 * i + 1] = __halves2half2(h2, h3);
    ((__half2*)lo)[2 * i]     = __halves2half2(l0, l1);
    ((__half2*)lo)[2 * i + 1] = __halves2half2(l2, l3);
}

// log2 of multiplicities
__global__ void logm_kernel(const float* __restrict__ m, float* __restrict__ lm, int n)
{
    int i = blockIdx.x * blockDim.x + threadIdx.x;
    if (i < n) lm[i] = log2f(m[i]);
}

// ---------------------------------------------------------------------------
// HMMA flash attention (no-max softmax in log2 domain).
// QK^T: split bf16 3-term. PV: single fp16. Output: fp16 single.
// ---------------------------------------------------------------------------
#define AT_QH 0
#define AT_QL 16384
#define AT_BUF0 32768
#define AT_KH 0
#define AT_KL 16384
#define AT_V  32768
#define AT_LM 49152
#define AT_BUFB 49664                 // per double-buffer stride
#define ATTN_SMEM (AT_BUF0 + 2 * AT_BUFB)   // 132096

__device__ __forceinline__ void attn_load_tile(
    uint32_t buf, int tid, int b, int h, int k0,
    const __nv_bfloat16* __restrict__ Kh, const __nv_bfloat16* __restrict__ Kl,
    const __half* __restrict__ V,
    const float* __restrict__ lm)
{
    #pragma unroll
    for (int i = 0; i < 4; i++) {
        int g   = tid + i * 256;        // 0..1023
        int row = g >> 3, kg = g & 7;
        uint32_t so = (uint32_t)(row * 128 + ((kg ^ (row & 7)) << 4));
        size_t gk = (size_t)(b * NKL + k0 + row) * ED + h * HD + kg * 8;
        cp16(buf + AT_KH + so, Kh + gk);
        cp16(buf + AT_KL + so, Kl + gk);
        cp16(buf + AT_V  + so, V + gk);
    }
    if (tid < 32)
        cp16(buf + AT_LM + tid * 16, lm + b * NKL + k0 + tid * 4);
    cp_commit();
}

__global__ __launch_bounds__(256, 1) void attn_mma(
    const __nv_bfloat16* __restrict__ Qh, const __nv_bfloat16* __restrict__ Ql,
    const __nv_bfloat16* __restrict__ Kh, const __nv_bfloat16* __restrict__ Kl,
    const __half* __restrict__ V,
    const float* __restrict__ logm,
    __half* __restrict__ O16)
{
    const uint32_t sb = smem_u32(dyn_smem);
    const int tid  = threadIdx.x;
    const int wid  = tid >> 5, lane = tid & 31;
    const int qt = blockIdx.x, h = blockIdx.y, b = blockIdx.z;
    const int q0 = qt * 128;
    const int m0 = wid * 16;

    const int rowA_in = (lane & 15);
    const int khA     = lane >> 4;
    const int nrow_in = ((lane & 16) >> 1) + (lane & 7);
    const int khB     = (lane >> 3) & 1;

    // Q tile load (q-rows 0..127, 64 d) hi/lo
    #pragma unroll
    for (int i = 0; i < 4; i++) {
        int g   = tid + i * 256;
        int row = g >> 3, kg = g & 7;
        uint32_t so = (uint32_t)(row * 128 + ((kg ^ (row & 7)) << 4));
        size_t gq = (size_t)(b * NQL + q0 + row) * ED + h * HD + kg * 8;
        cp16(sb + AT_QH + so, Qh + gq);
        cp16(sb + AT_QL + so, Ql + gq);
    }
    cp_commit();
    attn_load_tile(sb + AT_BUF0, tid, b, h, 0, Kh, Kl, V, logm);

    float oacc[8][4];
    #pragma unroll
    for (int j = 0; j < 8; j++)
        #pragma unroll
        for (int c = 0; c < 4; c++) oacc[j][c] = 0.0f;
    float lsum0 = 0.0f, lsum1 = 0.0f;

    const int NT = NKL / 128;   // 16
    for (int t = 0; t < NT; t++) {
        const uint32_t cur = sb + AT_BUF0 + (uint32_t)(t & 1) * AT_BUFB;
        if (t + 1 < NT) {
            attn_load_tile(sb + AT_BUF0 + (uint32_t)((t + 1) & 1) * AT_BUFB,
                           tid, b, h, (t + 1) * 128, Kh, Kl, V, logm);
            cp_wait1();
        } else {
            cp_wait0();
        }
        __syncthreads();

        // ---- S = Q K^T (split bf16, 3 terms)
        float s[16][4];
        #pragma unroll
        for (int j = 0; j < 16; j++)
            #pragma unroll
            for (int c = 0; c < 4; c++) s[j][c] = 0.0f;

        #pragma unroll
        for (int k16 = 0; k16 < 4; k16++) {
            uint32_t qah[4], qal[4];
            const int kgA = k16 * 2 + khA;
            {
                int rA = m0 + rowA_in;
                uint32_t off = (uint32_t)(rA * 128 + ((kgA ^ (rA & 7)) << 4));
                ldsm4(qah, sb + AT_QH + off);
                ldsm4(qal, sb + AT_QL + off);
            }
            const int kgB = k16 * 2 + khB;
            #pragma unroll
            for (int g = 0; g < 8; g++) {
                int nr = g * 16 + nrow_in;
                uint32_t off = (uint32_t)(nr * 128 + ((kgB ^ (nr & 7)) << 4));
                uint32_t bh[4], bl[4];
                ldsm4(bh, cur + AT_KH + off);
                ldsm4(bl, cur + AT_KL + off);
                mma16816(s[g * 2 + 0], qah, &bh[0]);
                mma16816(s[g * 2 + 0], qah, &bl[0]);
                mma16816(s[g * 2 + 0], qal, &bh[0]);
                mma16816(s[g * 2 + 1], qah, &bh[2]);
                mma16816(s[g * 2 + 1], qah, &bl[2]);
                mma16816(s[g * 2 + 1], qal, &bh[2]);
            }
        }

        // ---- p = 2^(s + log2 m), accumulate row sums
        const float* LmS = (const float*)(dyn_smem +
            (AT_BUF0 + (size_t)(t & 1) * AT_BUFB + AT_LM));
        #pragma unroll
        for (int j = 0; j < 16; j++) {
            float2 l2 = *(const float2*)&LmS[8 * j + (lane & 3) * 2];
            s[j][0] = fexp2(s[j][0] + l2.x);
            s[j][1] = fexp2(s[j][1] + l2.y);
            s[j][2] = fexp2(s[j][2] + l2.x);
            s[j][3] = fexp2(s[j][3] + l2.y);
            lsum0 += s[j][0] + s[j][1];
            lsum1 += s[j][2] + s[j][3];
        }

        // ---- O += P V (single fp16 term). P fragments built in-register.
        #pragma unroll
        for (int kt = 0; kt < 8; kt++) {
            uint32_t aph[4];
            aph[0] = packhf(s[2 * kt][0],     s[2 * kt][1]);
            aph[1] = packhf(s[2 * kt][2],     s[2 * kt][3]);
            aph[2] = packhf(s[2 * kt + 1][0], s[2 * kt + 1][1]);
            aph[3] = packhf(s[2 * kt + 1][2], s[2 * kt + 1][3]);

            #pragma unroll
            for (int j = 0; j < 4; j++) {   // d-chunk pairs (16 d per iter)
                int row = kt * 16 + (lane & 15);
                int ck  = 2 * j + (lane >> 4);
                uint32_t off = (uint32_t)(row * 128 + ((ck ^ (row & 7)) << 4));
                uint32_t vhf[4];
                ldsm4t(vhf, cur + AT_V + off);
                mma16816h(oacc[2 * j + 0], aph, &vhf[0]);
                mma16816h(oacc[2 * j + 1], aph, &vhf[2]);
            }
        }
        __syncthreads();
    }

    // ---- reduce row sums over the 4 lanes of each row quad
    #pragma unroll
    for (int off = 1; off <= 2; off <<= 1) {
        lsum0 += __shfl_xor_sync(0xffffffffu, lsum0, off);
        lsum1 += __shfl_xor_sync(0xffffffffu, lsum1, off);
    }
    const float inv0 = 1.0f / lsum0;
    const float inv1 = 1.0f / lsum1;

    // ---- normalize + fp16 write to [b, q, h*64 + d]
    const int row0 = q0 + m0 + (lane >> 2);
    const int col0 = h * HD + (lane & 3) * 2;
    #pragma unroll
    for (int j = 0; j < 8; j++) {
        int col = col0 + 8 * j;
        *(uint32_t*)&O16[(size_t)(b * NQL + row0) * ED + col] =
            packhf(oacc[j][0] * inv0, oacc[j][1] * inv0);
        *(uint32_t*)&O16[(size_t)(b * NQL + row0 + 8) * ED + col] =
            packhf(oacc[j][2] * inv1, oacc[j][3] * inv1);
    }
}

// ---------------------------------------------------------------------------
extern "C" void kernel_launch(void* const* d_in, const int* in_sizes, int n_in,
                              void* d_out, int out_size)
{
    const float* query = (const float*)d_in[0];
    const float* key   = (const float*)d_in[1];
    const float* value = (const float*)d_in[2];
    const float* kmult = (const float*)d_in[3];
    const float* wq_w  = (const float*)d_in[4];
    const float* wq_b  = (const float*)d_in[5];
    const float* wk_w  = (const float*)d_in[6];
    const float* wk_b  = (const float*)d_in[7];
    const float* wv_w  = (const float*)d_in[8];
    const float* wv_b  = (const float*)d_in[9];
    const float* wo_w  = (const float*)d_in[10];
    const float* wo_b  = (const float*)d_in[11];
    float* out = (float*)d_out;

    float* lm;
    cudaGetSymbolAddress((void**)&lm, g_logm);
    __nv_bfloat16 *xqh, *xql, *xkh, *xkl, *xvh, *xvl, *wh, *wl;
    __nv_bfloat16 *pqh, *pql, *pkh, *pkl;
    __half *pv16, *ao16, *woh, *wol;
    cudaGetSymbolAddress((void**)&xqh, g_xq_h);
    cudaGetSymbolAddress((void**)&xql, g_xq_l);
    cudaGetSymbolAddress((void**)&xkh, g_xk_h);
    cudaGetSymbolAddress((void**)&xkl, g_xk_l);
    cudaGetSymbolAddress((void**)&xvh, g_xv_h);
    cudaGetSymbolAddress((void**)&xvl, g_xv_l);
    cudaGetSymbolAddress((void**)&wh,  g_w_h);
    cudaGetSymbolAddress((void**)&wl,  g_w_l);
    cudaGetSymbolAddress((void**)&pqh, g_pq_h);
    cudaGetSymbolAddress((void**)&pql, g_pq_l);
    cudaGetSymbolAddress((void**)&pkh, g_pk_h);
    cudaGetSymbolAddress((void**)&pkl, g_pk_l);
    cudaGetSymbolAddress((void**)&pv16, g_pv16);
    cudaGetSymbolAddress((void**)&ao16, g_ao16);
    cudaGetSymbolAddress((void**)&woh, g_wo16h);
    cudaGetSymbolAddress((void**)&wol, g_wo16l);

    cudaFuncSetAttribute(gemm_mma,
                         cudaFuncAttributeMaxDynamicSharedMemorySize, GEMM_SMEM);
    cudaFuncSetAttribute(gemm_o,
                         cudaFuncAttributeMaxDynamicSharedMemorySize, GEMMO_SMEM);
    cudaFuncSetAttribute(attn_mma,
                         cudaFuncAttributeMaxDynamicSharedMemorySize, ATTN_SMEM);

    const int NQ4 = BB * NQL * ED / 4;
    const int NK4 = BB * NKL * ED / 4;
    const float QSCALE = 0.18033688011112042f;   // log2(e)/8

    // input conversions + log2(multiplicities)
    split4_kernel<<<(NQ4 + 255) / 256, 256>>>(query, xqh, xql, NQ4);
    split4_kernel<<<(NK4 + 255) / 256, 256>>>(key,   xkh, xkl, NK4);
    split4_kernel<<<(NK4 + 255) / 256, 256>>>(value, xvh, xvl, NK4);
    wsplit_kernel<<<(3 * ED * ED / 4 + 255) / 256, 256>>>(wq_w, wk_w, wv_w, wh, wl);
    wsplit16_kernel<<<(ED * ED / 4 + 255) / 256, 256>>>(wo_w, woh, wol);
    logm_kernel<<<(BB * NKL + 255) / 256, 256>>>(kmult, lm, BB * NKL);

    // Q/K projections -> split bf16; V projection -> single fp16
    {
        dim3 blk(256);
        dim3 gq(ED / GBN, (BB * NQL) / GBM);   // (8, 32)
        dim3 gk(ED / GBN, (BB * NKL) / GBM);   // (8, 64)
        gemm_mma<<<gq, blk, GEMM_SMEM>>>(xqh, xql, wh + 0 * ED * ED, wl + 0 * ED * ED,
                                         wq_b, pqh, pql, nullptr, QSCALE, 1);
        gemm_mma<<<gk, blk, GEMM_SMEM>>>(xkh, xkl, wh + 1 * ED * ED, wl + 1 * ED * ED,
                                         wk_b, pkh, pkl, nullptr, 1.0f, 1);
        gemm_mma<<<gk, blk, GEMM_SMEM>>>(xvh, xvl, wh + 2 * ED * ED, wl + 2 * ED * ED,
                                         wv_b, nullptr, nullptr, pv16, 1.0f, 2);
    }

    // attention (QK split bf16, PV single fp16) -> fp16 O
    {
        dim3 grid(NQL / 128, NH, BB);
        attn_mma<<<grid, 256, ATTN_SMEM>>>(pqh, pql, pkh, pkl, pv16, lm, ao16);
    }

    // output projection (A fp16 single, W fp16 2-term)
    {
        dim3 blk(256);
        dim3 go(ED / GBN, (BB * NQL) / GBM);
        gemm_o<<<go, blk, GEMMO_SMEM>>>(ao16, woh, wol, wo_b, out);
    }
}

// round 12
// speedup vs baseline: 3.9369x; 1.0656x over previous
#include <cuda_runtime.h>
#include <cuda_bf16.h>
#include <cuda_fp16.h>
#include <math.h>
#include <stdint.h>

#define BB 4
#define NH 16
#define HD 64
#define ED 1024
#define NQL 1024
#define NKL 2048

// ---------------------------------------------------------------------------
// Scratch (no cudaMalloc allowed)
// ---------------------------------------------------------------------------
__device__ float g_logm[BB * NKL];        // log2 multiplicities

// conversion outputs
__device__ __nv_bfloat16 g_xq_h[BB * NQL * ED], g_xq_l[BB * NQL * ED];
__device__ __nv_bfloat16 g_xk_h[BB * NKL * ED], g_xk_l[BB * NKL * ED];
__device__ __half        g_xv16[BB * NKL * ED];                       // value fp16
__device__ __nv_bfloat16 g_w_h[2 * ED * ED],    g_w_l[2 * ED * ED];   // wq, wk
__device__ __half        g_wv16h[ED * ED],      g_wv16l[ED * ED];     // wv fp16 split
__device__ __half        g_wo16h[ED * ED],      g_wo16l[ED * ED];     // wo fp16 split

// projected outputs
__device__ __nv_bfloat16 g_pq_h[BB * NQL * ED], g_pq_l[BB * NQL * ED];
__device__ __nv_bfloat16 g_pk_h[BB * NKL * ED], g_pk_l[BB * NKL * ED];
__device__ __half        g_pv16[BB * NKL * ED];     // V fp16 single
__device__ __half        g_ao16[BB * NQL * ED];     // attention out fp16 single

// single dynamic-smem symbol for the whole TU
extern __shared__ char dyn_smem[];

// ---------------------------------------------------------------------------
// helpers
// ---------------------------------------------------------------------------
__device__ __forceinline__ uint32_t smem_u32(const void* p) {
    uint32_t a;
    asm("{ .reg .u64 t; cvta.to.shared.u64 t, %1; cvt.u32.u64 %0, t; }"
        : "=r"(a) : "l"(p));
    return a;
}
__device__ __forceinline__ void cp16(uint32_t dst, const void* src) {
    asm volatile("cp.async.cg.shared.global [%0], [%1], 16;"
                 :: "r"(dst), "l"(src));
}
__device__ __forceinline__ void cp_commit() {
    asm volatile("cp.async.commit_group;");
}
__device__ __forceinline__ void cp_wait1() {
    asm volatile("cp.async.wait_group 1;" ::: "memory");
}
__device__ __forceinline__ void cp_wait0() {
    asm volatile("cp.async.wait_group 0;" ::: "memory");
}
__device__ __forceinline__ void ldsm4(uint32_t* r, uint32_t addr) {
    asm volatile("ldmatrix.sync.aligned.m8n8.x4.shared.b16 {%0,%1,%2,%3}, [%4];"
                 : "=r"(r[0]), "=r"(r[1]), "=r"(r[2]), "=r"(r[3]) : "r"(addr));
}
__device__ __forceinline__ void ldsm4t(uint32_t* r, uint32_t addr) {
    asm volatile("ldmatrix.sync.aligned.m8n8.x4.trans.shared.b16 {%0,%1,%2,%3}, [%4];"
                 : "=r"(r[0]), "=r"(r[1]), "=r"(r[2]), "=r"(r[3]) : "r"(addr));
}
__device__ __forceinline__ void mma16816(float* c, const uint32_t* a, const uint32_t* b) {
    asm volatile(
        "mma.sync.aligned.m16n8k16.row.col.f32.bf16.bf16.f32 "
        "{%0,%1,%2,%3}, {%4,%5,%6,%7}, {%8,%9}, {%0,%1,%2,%3};"
        : "+f"(c[0]), "+f"(c[1]), "+f"(c[2]), "+f"(c[3])
        : "r"(a[0]), "r"(a[1]), "r"(a[2]), "r"(a[3]), "r"(b[0]), "r"(b[1]));
}
__device__ __forceinline__ void mma16816h(float* c, const uint32_t* a, const uint32_t* b) {
    asm volatile(
        "mma.sync.aligned.m16n8k16.row.col.f32.f16.f16.f32 "
        "{%0,%1,%2,%3}, {%4,%5,%6,%7}, {%8,%9}, {%0,%1,%2,%3};"
        : "+f"(c[0]), "+f"(c[1]), "+f"(c[2]), "+f"(c[3])
        : "r"(a[0]), "r"(a[1]), "r"(a[2]), "r"(a[3]), "r"(b[0]), "r"(b[1]));
}
// pack (lo, hi) floats -> bf16x2 (lo in low half)
__device__ __forceinline__ uint32_t packbf(float lo, float hi) {
    uint32_t r;
    asm("cvt.rn.bf16x2.f32 %0, %1, %2;" : "=r"(r) : "f"(hi), "f"(lo));
    return r;
}
// residual pack: (lo,hi) minus the bf16 values already packed in h
__device__ __forceinline__ uint32_t packlo(uint32_t h, float lo, float hi) {
    float hl = __int_as_float(h << 16);
    float hh = __int_as_float(h & 0xFFFF0000u);
    return packbf(lo - hl, hi - hh);
}
// pack (lo, hi) floats -> f16x2 (lo in low half)
__device__ __forceinline__ uint32_t packhf(float lo, float hi) {
    uint32_t r;
    asm("cvt.rn.f16x2.f32 %0, %1, %2;" : "=r"(r) : "f"(hi), "f"(lo));
    return r;
}
// fast 2^x on the FMA pipe (no MUFU). |err| ~ 2.4e-6 rel. x >= -126 clamped.
__device__ __forceinline__ float fexp2(float x) {
    x = fmaxf(x, -126.0f);
    float z = x + 12582912.0f;                 // round-to-nearest-int via magic
    int   n = __float_as_int(z) - 0x4B400000;
    float f = x - (z - 12582912.0f);           // f in [-0.5, 0.5]
    float p = 0.0013333558f;
    p = fmaf(p, f, 0.0096181291f);
    p = fmaf(p, f, 0.0555041087f);
    p = fmaf(p, f, 0.2402265070f);
    p = fmaf(p, f, 0.6931471806f);
    p = fmaf(p, f, 1.0f);
    return __int_as_float(__float_as_int(p) + (n << 23));
}

// ---------------------------------------------------------------------------
// split-bf16 HMMA GEMM:  C[M,1024] = A[M,1024] @ W[1024,1024]^T + bias
// writes split bf16 (Chi, Clo) of (C+bias)*scale.
// ---------------------------------------------------------------------------
#define GBM 128
#define GBN 128
#define GBK 64
#define GNCH (ED / GBK)             // 16
#define TILE_B (GBM * GBK * 2)      // 16384 bytes
#define OFF_AH 0
#define OFF_AL (1 * TILE_B)
#define OFF_WH (2 * TILE_B)
#define OFF_WL (3 * TILE_B)
#define GBUF_B (4 * TILE_B)         // 65536
#define GEMM_SMEM (2 * GBUF_B)      // 131072

__device__ __forceinline__ void g_load_chunk(
    uint32_t buf, int tid, int bm, int bn, int k0,
    const __nv_bfloat16* __restrict__ Ah, const __nv_bfloat16* __restrict__ Al,
    const __nv_bfloat16* __restrict__ Wh, const __nv_bfloat16* __restrict__ Wl)
{
    #pragma unroll
    for (int i = 0; i < 4; i++) {
        int g   = tid + i * 256;        // 0..1023
        int row = g >> 3, kg = g & 7;
        uint32_t so = (uint32_t)(row * 128 + ((kg ^ (row & 7)) << 4));
        size_t ga = (size_t)(bm + row) * ED + k0 + kg * 8;
        size_t gw = (size_t)(bn + row) * ED + k0 + kg * 8;
        cp16(buf + OFF_AH + so, Ah + ga);
        cp16(buf + OFF_AL + so, Al + ga);
        cp16(buf + OFF_WH + so, Wh + gw);
        cp16(buf + OFF_WL + so, Wl + gw);
    }
    cp_commit();
}

__global__ __launch_bounds__(256, 1) void gemm_mma(
    const __nv_bfloat16* __restrict__ Ah, const __nv_bfloat16* __restrict__ Al,
    const __nv_bfloat16* __restrict__ Wh, const __nv_bfloat16* __restrict__ Wl,
    const float* __restrict__ bias,
    __nv_bfloat16* __restrict__ Chi, __nv_bfloat16* __restrict__ Clo,
    float scale)
{
    const uint32_t sb = smem_u32(dyn_smem);
    const int tid  = threadIdx.x;
    const int wid  = tid >> 5, lane = tid & 31;
    const int wm   = wid & 3, wn = wid >> 2;
    const int m0   = wm * 32, n0 = wn * 64;
    const int bm   = blockIdx.y * GBM;
    const int bn   = blockIdx.x * GBN;

    float acc[2][8][4];
    #pragma unroll
    for (int a = 0; a < 2; a++)
        #pragma unroll
        for (int b = 0; b < 8; b++)
            #pragma unroll
            for (int c = 0; c < 4; c++) acc[a][b][c] = 0.0f;

    const int rowA_in = (lane & 15);
    const int khA     = lane >> 4;
    const int nrow_in = ((lane & 16) >> 1) + (lane & 7);
    const int khB     = (lane >> 3) & 1;

    g_load_chunk(sb, tid, bm, bn, 0, Ah, Al, Wh, Wl);

    for (int ch = 0; ch < GNCH; ch++) {
        const uint32_t cur = sb + (uint32_t)(ch & 1) * GBUF_B;
        if (ch + 1 < GNCH) {
            g_load_chunk(sb + (uint32_t)((ch + 1) & 1) * GBUF_B, tid, bm, bn,
                         (ch + 1) * GBK, Ah, Al, Wh, Wl);
            cp_wait1();
        } else {
            cp_wait0();
        }
        __syncthreads();

        #pragma unroll
        for (int k16 = 0; k16 < 4; k16++) {
            uint32_t ah[2][4], al[2][4];
            const int kgA = k16 * 2 + khA;
            #pragma unroll
            for (int mt = 0; mt < 2; mt++) {
                int rA = m0 + mt * 16 + rowA_in;
                uint32_t off = (uint32_t)(rA * 128 + ((kgA ^ (rA & 7)) << 4));
                ldsm4(ah[mt], cur + OFF_AH + off);
                ldsm4(al[mt], cur + OFF_AL + off);
            }
            const int kgB = k16 * 2 + khB;
            #pragma unroll
            for (int g = 0; g < 4; g++) {
                int nr = n0 + g * 16 + nrow_in;
                uint32_t off = (uint32_t)(nr * 128 + ((kgB ^ (nr & 7)) << 4));
                uint32_t bh[4], bl[4];
                ldsm4(bh, cur + OFF_WH + off);
                ldsm4(bl, cur + OFF_WL + off);
                #pragma unroll
                for (int mt = 0; mt < 2; mt++) {
                    mma16816(acc[mt][g * 2 + 0], ah[mt], &bh[0]);
                    mma16816(acc[mt][g * 2 + 0], ah[mt], &bl[0]);
                    mma16816(acc[mt][g * 2 + 0], al[mt], &bh[0]);
                    mma16816(acc[mt][g * 2 + 1], ah[mt], &bh[2]);
                    mma16816(acc[mt][g * 2 + 1], ah[mt], &bl[2]);
                    mma16816(acc[mt][g * 2 + 1], al[mt], &bh[2]);
                }
            }
        }
        __syncthreads();
    }

    const int lr = lane >> 2;
    const int lc = (lane & 3) * 2;
    #pragma unroll
    for (int mt = 0; mt < 2; mt++) {
        #pragma unroll
        for (int nt = 0; nt < 8; nt++) {
            int row = bm + m0 + mt * 16 + lr;
            int col = bn + n0 + nt * 8 + lc;
            float2 b2 = *(const float2*)&bias[col];
            float vx = (acc[mt][nt][0] + b2.x) * scale;
            float vy = (acc[mt][nt][1] + b2.y) * scale;
            float wx = (acc[mt][nt][2] + b2.x) * scale;
            float wy = (acc[mt][nt][3] + b2.y) * scale;
            uint32_t h0 = packbf(vx, vy);
            uint32_t l0 = packlo(h0, vx, vy);
            uint32_t h1 = packbf(wx, wy);
            uint32_t l1 = packlo(h1, wx, wy);
            *(uint32_t*)&Chi[(size_t)row * ED + col]       = h0;
            *(uint32_t*)&Clo[(size_t)row * ED + col]       = l0;
            *(uint32_t*)&Chi[(size_t)(row + 8) * ED + col] = h1;
            *(uint32_t*)&Clo[(size_t)(row + 8) * ED + col] = l1;
        }
    }
}

// ---------------------------------------------------------------------------
// fp16 GEMM: A fp16 single x W fp16 2-term split.
// mode 0: fp32 out + bias.  mode 2: fp16 out (+bias).
// Used for both the V projection and the O projection.
// ---------------------------------------------------------------------------
#define GO_A 0
#define GO_WH TILE_B
#define GO_WL (2 * TILE_B)
#define GO_BUF (3 * TILE_B)          // 49152
#define GEMMO_SMEM (2 * GO_BUF)      // 98304

__device__ __forceinline__ void o_load_chunk(
    uint32_t buf, int tid, int bm, int bn, int k0,
    const __half* __restrict__ A,
    const __half* __restrict__ Wh, const __half* __restrict__ Wl)
{
    #pragma unroll
    for (int i = 0; i < 4; i++) {
        int g   = tid + i * 256;
        int row = g >> 3, kg = g & 7;
        uint32_t so = (uint32_t)(row * 128 + ((kg ^ (row & 7)) << 4));
        size_t ga = (size_t)(bm + row) * ED + k0 + kg * 8;
        size_t gw = (size_t)(bn + row) * ED + k0 + kg * 8;
        cp16(buf + GO_A + so, A + ga);
        cp16(buf + GO_WH + so, Wh + gw);
        cp16(buf + GO_WL + so, Wl + gw);
    }
    cp_commit();
}

__global__ __launch_bounds__(256, 1) void gemm_o(
    const __half* __restrict__ A,
    const __half* __restrict__ Wh, const __half* __restrict__ Wl,
    const float* __restrict__ bias, float* __restrict__ C,
    __half* __restrict__ C16, int mode)
{
    const uint32_t sb = smem_u32(dyn_smem);
    const int tid  = threadIdx.x;
    const int wid  = tid >> 5, lane = tid & 31;
    const int wm   = wid & 3, wn = wid >> 2;
    const int m0   = wm * 32, n0 = wn * 64;
    const int bm   = blockIdx.y * GBM;
    const int bn   = blockIdx.x * GBN;

    float acc[2][8][4];
    #pragma unroll
    for (int a = 0; a < 2; a++)
        #pragma unroll
        for (int b = 0; b < 8; b++)
            #pragma unroll
            for (int c = 0; c < 4; c++) acc[a][b][c] = 0.0f;

    const int rowA_in = (lane & 15);
    const int khA     = lane >> 4;
    const int nrow_in = ((lane & 16) >> 1) + (lane & 7);
    const int khB     = (lane >> 3) & 1;

    o_load_chunk(sb, tid, bm, bn, 0, A, Wh, Wl);

    for (int ch = 0; ch < GNCH; ch++) {
        const uint32_t cur = sb + (uint32_t)(ch & 1) * GO_BUF;
        if (ch + 1 < GNCH) {
            o_load_chunk(sb + (uint32_t)((ch + 1) & 1) * GO_BUF, tid, bm, bn,
                         (ch + 1) * GBK, A, Wh, Wl);
            cp_wait1();
        } else {
            cp_wait0();
        }
        __syncthreads();

        #pragma unroll
        for (int k16 = 0; k16 < 4; k16++) {
            uint32_t ah[2][4];
            const int kgA = k16 * 2 + khA;
            #pragma unroll
            for (int mt = 0; mt < 2; mt++) {
                int rA = m0 + mt * 16 + rowA_in;
                uint32_t off = (uint32_t)(rA * 128 + ((kgA ^ (rA & 7)) << 4));
                ldsm4(ah[mt], cur + GO_A + off);
            }
            const int kgB = k16 * 2 + khB;
            #pragma unroll
            for (int g = 0; g < 4; g++) {
                int nr = n0 + g * 16 + nrow_in;
                uint32_t off = (uint32_t)(nr * 128 + ((kgB ^ (nr & 7)) << 4));
                uint32_t bh[4], bl[4];
                ldsm4(bh, cur + GO_WH + off);
                ldsm4(bl, cur + GO_WL + off);
                #pragma unroll
                for (int mt = 0; mt < 2; mt++) {
                    mma16816h(acc[mt][g * 2 + 0], ah[mt], &bh[0]);
                    mma16816h(acc[mt][g * 2 + 0], ah[mt], &bl[0]);
                    mma16816h(acc[mt][g * 2 + 1], ah[mt], &bh[2]);
                    mma16816h(acc[mt][g * 2 + 1], ah[mt], &bl[2]);
                }
            }
        }
        __syncthreads();
    }

    const int lr = lane >> 2;
    const int lc = (lane & 3) * 2;
    #pragma unroll
    for (int mt = 0; mt < 2; mt++) {
        #pragma unroll
        for (int nt = 0; nt < 8; nt++) {
            int row = bm + m0 + mt * 16 + lr;
            int col = bn + n0 + nt * 8 + lc;
            float2 b2 = *(const float2*)&bias[col];
            float vx = acc[mt][nt][0] + b2.x;
            float vy = acc[mt][nt][1] + b2.y;
            float wx = acc[mt][nt][2] + b2.x;
            float wy = acc[mt][nt][3] + b2.y;
            if (mode == 0) {
                *(float2*)&C[(size_t)row * ED + col]       = make_float2(vx, vy);
                *(float2*)&C[(size_t)(row + 8) * ED + col] = make_float2(wx, wy);
            } else {
                *(uint32_t*)&C16[(size_t)row * ED + col]       = packhf(vx, vy);
                *(uint32_t*)&C16[(size_t)(row + 8) * ED + col] = packhf(wx, wy);
            }
        }
    }
}

// ---------------------------------------------------------------------------
// conversions
// ---------------------------------------------------------------------------
__global__ void split4_kernel(const float* __restrict__ x,
                              __nv_bfloat16* __restrict__ hi,
                              __nv_bfloat16* __restrict__ lo, int n4)
{
    int i = blockIdx.x * blockDim.x + threadIdx.x;
    if (i >= n4) return;
    float4 v = ((const float4*)x)[i];
    uint32_t h0 = packbf(v.x, v.y);
    uint32_t l0 = packlo(h0, v.x, v.y);
    uint32_t h1 = packbf(v.z, v.w);
    uint32_t l1 = packlo(h1, v.z, v.w);
    ((uint32_t*)hi)[2 * i]     = h0;
    ((uint32_t*)hi)[2 * i + 1] = h1;
    ((uint32_t*)lo)[2 * i]     = l0;
    ((uint32_t*)lo)[2 * i + 1] = l1;
}

// fp32 -> fp16 single
__global__ void cast16_kernel(const float* __restrict__ x,
                              __half* __restrict__ y, int n4)
{
    int i = blockIdx.x * blockDim.x + threadIdx.x;
    if (i >= n4) return;
    float4 v = ((const float4*)x)[i];
    ((uint32_t*)y)[2 * i]     = packhf(v.x, v.y);
    ((uint32_t*)y)[2 * i + 1] = packhf(v.z, v.w);
}

__global__ void wsplit_kernel(const float* __restrict__ w0, const float* __restrict__ w1,
                              __nv_bfloat16* __restrict__ hi,
                              __nv_bfloat16* __restrict__ lo)
{
    int i = blockIdx.x * blockDim.x + threadIdx.x;
    if (i >= 2 * ED * ED / 4) return;
    int which = i >> 18;
    int off = i & 262143;
    const float* w = which == 0 ? w0 : w1;
    float4 v = ((const float4*)w)[off];
    uint32_t h0 = packbf(v.x, v.y);
    uint32_t l0 = packlo(h0, v.x, v.y);
    uint32_t h1 = packbf(v.z, v.w);
    uint32_t l1 = packlo(h1, v.z, v.w);
    ((uint32_t*)hi)[2 * i]     = h0;
    ((uint32_t*)hi)[2 * i + 1] = h1;
    ((uint32_t*)lo)[2 * i]     = l0;
    ((uint32_t*)lo)[2 * i + 1] = l1;
}

// w -> fp16 hi/lo split (two weights in one launch)
__global__ void wsplit16_kernel(const float* __restrict__ w0, const float* __restrict__ w1,
                                __half* __restrict__ hi0, __half* __restrict__ lo0,
                                __half* __restrict__ hi1, __half* __restrict__ lo1)
{
    int i = blockIdx.x * blockDim.x + threadIdx.x;
    if (i >= 2 * ED * ED / 4) return;
    int which = i >> 18;
    int off = i & 262143;
    const float* w = which == 0 ? w0 : w1;
    __half* hi = which == 0 ? hi0 : hi1;
    __half* lo = which == 0 ? lo0 : lo1;
    float4 v = ((const float4*)w)[off];
    __half h0 = __float2half(v.x), h1 = __float2half(v.y);
    __half h2 = __float2half(v.z), h3 = __float2half(v.w);
    __half l0 = __float2half(v.x - __half2float(h0));
    __half l1 = __float2half(v.y - __half2float(h1));
    __half l2 = __float2half(v.z - __half2float(h2));
    __half l3 = __float2half(v.w - __half2float(h3));
    ((__half2*)hi)[2 * off]     = __halves2half2(h0, h1);
    ((__half2*)hi)[2 * off + 1] = __halves2half2(h2, h3);
    ((__half2*)lo)[2 * off]     = __halves2half2(l0, l1);
    ((__half2*)lo)[2 * off + 1] = __halves2half2(l2, l3);
}

// log2 of multiplicities
__global__ void logm_kernel(const float* __restrict__ m, float* __restrict__ lm, int n)
{
    int i = blockIdx.x * blockDim.x + threadIdx.x;
    if (i < n) lm[i] = log2f(m[i]);
}

// ---------------------------------------------------------------------------
// HMMA flash attention (no-max softmax in log2 domain).
// QK^T: split bf16 3-term. PV: single fp16. Output: fp16 single.
// ---------------------------------------------------------------------------
#define AT_QH 0
#define AT_QL 16384
#define AT_BUF0 32768
#define AT_KH 0
#define AT_KL 16384
#define AT_V  32768
#define AT_LM 49152
#define AT_BUFB 49664                 // per double-buffer stride
#define ATTN_SMEM (AT_BUF0 + 2 * AT_BUFB)   // 132096

__device__ __forceinline__ void attn_load_tile(
    uint32_t buf, int tid, int b, int h, int k0,
    const __nv_bfloat16* __restrict__ Kh, const __nv_bfloat16* __restrict__ Kl,
    const __half* __restrict__ V,
    const float* __restrict__ lm)
{
    #pragma unroll
    for (int i = 0; i < 4; i++) {
        int g   = tid + i * 256;        // 0..1023
        int row = g >> 3, kg = g & 7;
        uint32_t so = (uint32_t)(row * 128 + ((kg ^ (row & 7)) << 4));
        size_t gk = (size_t)(b * NKL + k0 + row) * ED + h * HD + kg * 8;
        cp16(buf + AT_KH + so, Kh + gk);
        cp16(buf + AT_KL + so, Kl + gk);
        cp16(buf + AT_V  + so, V + gk);
    }
    if (tid < 32)
        cp16(buf + AT_LM + tid * 16, lm + b * NKL + k0 + tid * 4);
    cp_commit();
}

__global__ __launch_bounds__(256, 1) void attn_mma(
    const __nv_bfloat16* __restrict__ Qh, const __nv_bfloat16* __restrict__ Ql,
    const __nv_bfloat16* __restrict__ Kh, const __nv_bfloat16* __restrict__ Kl,
    const __half* __restrict__ V,
    const float* __restrict__ logm,
    __half* __restrict__ O16)
{
    const uint32_t sb = smem_u32(dyn_smem);
    const int tid  = threadIdx.x;
    const int wid  = tid >> 5, lane = tid & 31;
    const int qt = blockIdx.x, h = blockIdx.y, b = blockIdx.z;
    const int q0 = qt * 128;
    const int m0 = wid * 16;

    const int rowA_in = (lane & 15);
    const int khA     = lane >> 4;
    const int nrow_in = ((lane & 16) >> 1) + (lane & 7);
    const int khB     = (lane >> 3) & 1;

    // Q tile load (q-rows 0..127, 64 d) hi/lo
    #pragma unroll
    for (int i = 0; i < 4; i++) {
        int g   = tid + i * 256;
        int row = g >> 3, kg = g & 7;
        uint32_t so = (uint32_t)(row * 128 + ((kg ^ (row & 7)) << 4));
        size_t gq = (size_t)(b * NQL + q0 + row) * ED + h * HD + kg * 8;
        cp16(sb + AT_QH + so, Qh + gq);
        cp16(sb + AT_QL + so, Ql + gq);
    }
    cp_commit();
    attn_load_tile(sb + AT_BUF0, tid, b, h, 0, Kh, Kl, V, logm);

    float oacc[8][4];
    #pragma unroll
    for (int j = 0; j < 8; j++)
        #pragma unroll
        for (int c = 0; c < 4; c++) oacc[j][c] = 0.0f;
    float lsum0 = 0.0f, lsum1 = 0.0f;

    const int NT = NKL / 128;   // 16
    for (int t = 0; t < NT; t++) {
        const uint32_t cur = sb + AT_BUF0 + (uint32_t)(t & 1) * AT_BUFB;
        if (t + 1 < NT) {
            attn_load_tile(sb + AT_BUF0 + (uint32_t)((t + 1) & 1) * AT_BUFB,
                           tid, b, h, (t + 1) * 128, Kh, Kl, V, logm);
            cp_wait1();
        } else {
            cp_wait0();
        }
        __syncthreads();

        // ---- S = Q K^T (split bf16, 3 terms)
        float s[16][4];
        #pragma unroll
        for (int j = 0; j < 16; j++)
            #pragma unroll
            for (int c = 0; c < 4; c++) s[j][c] = 0.0f;

        #pragma unroll
        for (int k16 = 0; k16 < 4; k16++) {
            uint32_t qah[4], qal[4];
            const int kgA = k16 * 2 + khA;
            {
                int rA = m0 + rowA_in;
                uint32_t off = (uint32_t)(rA * 128 + ((kgA ^ (rA & 7)) << 4));
                ldsm4(qah, sb + AT_QH + off);
                ldsm4(qal, sb + AT_QL + off);
            }
            const int kgB = k16 * 2 + khB;
            #pragma unroll
            for (int g = 0; g < 8; g++) {
                int nr = g * 16 + nrow_in;
                uint32_t off = (uint32_t)(nr * 128 + ((kgB ^ (nr & 7)) << 4));
                uint32_t bh[4], bl[4];
                ldsm4(bh, cur + AT_KH + off);
                ldsm4(bl, cur + AT_KL + off);
                mma16816(s[g * 2 + 0], qah, &bh[0]);
                mma16816(s[g * 2 + 0], qah, &bl[0]);
                mma16816(s[g * 2 + 0], qal, &bh[0]);
                mma16816(s[g * 2 + 1], qah, &bh[2]);
                mma16816(s[g * 2 + 1], qah, &bl[2]);
                mma16816(s[g * 2 + 1], qal, &bh[2]);
            }
        }

        // ---- p = 2^(s + log2 m), accumulate row sums
        const float* LmS = (const float*)(dyn_smem +
            (AT_BUF0 + (size_t)(t & 1) * AT_BUFB + AT_LM));
        #pragma unroll
        for (int j = 0; j < 16; j++) {
            float2 l2 = *(const float2*)&LmS[8 * j + (lane & 3) * 2];
            s[j][0] = fexp2(s[j][0] + l2.x);
            s[j][1] = fexp2(s[j][1] + l2.y);
            s[j][2] = fexp2(s[j][2] + l2.x);
            s[j][3] = fexp2(s[j][3] + l2.y);
            lsum0 += s[j][0] + s[j][1];
            lsum1 += s[j][2] + s[j][3];
        }

        // ---- O += P V (single fp16 term). P fragments built in-register.
        #pragma unroll
        for (int kt = 0; kt < 8; kt++) {
            uint32_t aph[4];
            aph[0] = packhf(s[2 * kt][0],     s[2 * kt][1]);
            aph[1] = packhf(s[2 * kt][2],     s[2 * kt][3]);
            aph[2] = packhf(s[2 * kt + 1][0], s[2 * kt + 1][1]);
            aph[3] = packhf(s[2 * kt + 1][2], s[2 * kt + 1][3]);

            #pragma unroll
            for (int j = 0; j < 4; j++) {   // d-chunk pairs (16 d per iter)
                int row = kt * 16 + (lane & 15);
                int ck  = 2 * j + (lane >> 4);
                uint32_t off = (uint32_t)(row * 128 + ((ck ^ (row & 7)) << 4));
                uint32_t vhf[4];
                ldsm4t(vhf, cur + AT_V + off);
                mma16816h(oacc[2 * j + 0], aph, &vhf[0]);
                mma16816h(oacc[2 * j + 1], aph, &vhf[2]);
            }
        }
        __syncthreads();
    }

    // ---- reduce row sums over the 4 lanes of each row quad
    #pragma unroll
    for (int off = 1; off <= 2; off <<= 1) {
        lsum0 += __shfl_xor_sync(0xffffffffu, lsum0, off);
        lsum1 += __shfl_xor_sync(0xffffffffu, lsum1, off);
    }
    const float inv0 = 1.0f / lsum0;
    const float inv1 = 1.0f / lsum1;

    // ---- normalize + fp16 write to [b, q, h*64 + d]
    const int row0 = q0 + m0 + (lane >> 2);
    const int col0 = h * HD + (lane & 3) * 2;
    #pragma unroll
    for (int j = 0; j < 8; j++) {
        int col = col0 + 8 * j;
        *(uint32_t*)&O16[(size_t)(b * NQL + row0) * ED + col] =
            packhf(oacc[j][0] * inv0, oacc[j][1] * inv0);
        *(uint32_t*)&O16[(size_t)(b * NQL + row0 + 8) * ED + col] =
            packhf(oacc[j][2] * inv1, oacc[j][3] * inv1);
    }
}

// ---------------------------------------------------------------------------
extern "C" void kernel_launch(void* const* d_in, const int* in_sizes, int n_in,
                              void* d_out, int out_size)
{
    const float* query = (const float*)d_in[0];
    const float* key   = (const float*)d_in[1];
    const float* value = (const float*)d_in[2];
    const float* kmult = (const float*)d_in[3];
    const float* wq_w  = (const float*)d_in[4];
    const float* wq_b  = (const float*)d_in[5];
    const float* wk_w  = (const float*)d_in[6];
    const float* wk_b  = (const float*)d_in[7];
    const float* wv_w  = (const float*)d_in[8];
    const float* wv_b  = (const float*)d_in[9];
    const float* wo_w  = (const float*)d_in[10];
    const float* wo_b  = (const float*)d_in[11];
    float* out = (float*)d_out;

    float* lm;
    cudaGetSymbolAddress((void**)&lm, g_logm);
    __nv_bfloat16 *xqh, *xql, *xkh, *xkl, *wh, *wl;
    __nv_bfloat16 *pqh, *pql, *pkh, *pkl;
    __half *xv16, *pv16, *ao16, *wvh, *wvl, *woh, *wol;
    cudaGetSymbolAddress((void**)&xqh, g_xq_h);
    cudaGetSymbolAddress((void**)&xql, g_xq_l);
    cudaGetSymbolAddress((void**)&xkh, g_xk_h);
    cudaGetSymbolAddress((void**)&xkl, g_xk_l);
    cudaGetSymbolAddress((void**)&xv16, g_xv16);
    cudaGetSymbolAddress((void**)&wh,  g_w_h);
    cudaGetSymbolAddress((void**)&wl,  g_w_l);
    cudaGetSymbolAddress((void**)&pqh, g_pq_h);
    cudaGetSymbolAddress((void**)&pql, g_pq_l);
    cudaGetSymbolAddress((void**)&pkh, g_pk_h);
    cudaGetSymbolAddress((void**)&pkl, g_pk_l);
    cudaGetSymbolAddress((void**)&pv16, g_pv16);
    cudaGetSymbolAddress((void**)&ao16, g_ao16);
    cudaGetSymbolAddress((void**)&wvh, g_wv16h);
    cudaGetSymbolAddress((void**)&wvl, g_wv16l);
    cudaGetSymbolAddress((void**)&woh, g_wo16h);
    cudaGetSymbolAddress((void**)&wol, g_wo16l);

    cudaFuncSetAttribute(gemm_mma,
                         cudaFuncAttributeMaxDynamicSharedMemorySize, GEMM_SMEM);
    cudaFuncSetAttribute(gemm_o,
                         cudaFuncAttributeMaxDynamicSharedMemorySize, GEMMO_SMEM);
    cudaFuncSetAttribute(attn_mma,
                         cudaFuncAttributeMaxDynamicSharedMemorySize, ATTN_SMEM);

    const int NQ4 = BB * NQL * ED / 4;
    const int NK4 = BB * NKL * ED / 4;
    const float QSCALE = 0.18033688011112042f;   // log2(e)/8

    // input conversions + log2(multiplicities)
    split4_kernel<<<(NQ4 + 255) / 256, 256>>>(query, xqh, xql, NQ4);
    split4_kernel<<<(NK4 + 255) / 256, 256>>>(key,   xkh, xkl, NK4);
    cast16_kernel<<<(NK4 + 255) / 256, 256>>>(value, xv16, NK4);
    wsplit_kernel<<<(2 * ED * ED / 4 + 255) / 256, 256>>>(wq_w, wk_w, wh, wl);
    wsplit16_kernel<<<(2 * ED * ED / 4 + 255) / 256, 256>>>(wv_w, wo_w, wvh, wvl, woh, wol);
    logm_kernel<<<(BB * NKL + 255) / 256, 256>>>(kmult, lm, BB * NKL);

    // Q/K projections -> split bf16 (3-term); V projection -> fp16 (2-term)
    {
        dim3 blk(256);
        dim3 gq(ED / GBN, (BB * NQL) / GBM);   // (8, 32)
        dim3 gk(ED / GBN, (BB * NKL) / GBM);   // (8, 64)
        gemm_mma<<<gq, blk, GEMM_SMEM>>>(xqh, xql, wh + 0 * ED * ED, wl + 0 * ED * ED,
                                         wq_b, pqh, pql, QSCALE);
        gemm_mma<<<gk, blk, GEMM_SMEM>>>(xkh, xkl, wh + 1 * ED * ED, wl + 1 * ED * ED,
                                         wk_b, pkh, pkl, 1.0f);
        gemm_o<<<gk, blk, GEMMO_SMEM>>>(xv16, wvh, wvl, wv_b, nullptr, pv16, 2);
    }

    // attention (QK split bf16, PV single fp16) -> fp16 O
    {
        dim3 grid(NQL / 128, NH, BB);
        attn_mma<<<grid, 256, ATTN_SMEM>>>(pqh, pql, pkh, pkl, pv16, lm, ao16);
    }

    // output projection (A fp16 single, W fp16 2-term) -> fp32 out
    {
        dim3 blk(256);
        dim3 go(ED / GBN, (BB * NQL) / GBM);
        gemm_o<<<go, blk, GEMMO_SMEM>>>(ao16, woh, wol, wo_b, out, nullptr, 0);
    }
}

// round 13
// speedup vs baseline: 4.3710x; 1.1103x over previous
#include <cuda_runtime.h>
#include <cuda_bf16.h>
#include <cuda_fp16.h>
#include <math.h>
#include <stdint.h>

#define BB 4
#define NH 16
#define HD 64
#define ED 1024
#define NQL 1024
#define NKL 2048

// ---------------------------------------------------------------------------
// Scratch (no cudaMalloc allowed)
// ---------------------------------------------------------------------------
__device__ float g_logm[BB * NKL];        // log2 multiplicities

// conversion outputs
__device__ __half g_xq16[BB * NQL * ED];              // query fp16
__device__ __half g_xk16[BB * NKL * ED];              // key fp16
__device__ __half g_xv16[BB * NKL * ED];              // value fp16
__device__ __half g_w16h[4 * ED * ED], g_w16l[4 * ED * ED];  // wq,wk,wv,wo fp16 split

// projected outputs
__device__ __nv_bfloat16 g_pq_h[BB * NQL * ED], g_pq_l[BB * NQL * ED];
__device__ __nv_bfloat16 g_pk_h[BB * NKL * ED], g_pk_l[BB * NKL * ED];
__device__ __half        g_pv16[BB * NKL * ED];     // V fp16 single
__device__ __half        g_ao16[BB * NQL * ED];     // attention out fp16 single

// single dynamic-smem symbol for the whole TU
extern __shared__ char dyn_smem[];

// ---------------------------------------------------------------------------
// helpers
// ---------------------------------------------------------------------------
__device__ __forceinline__ uint32_t smem_u32(const void* p) {
    uint32_t a;
    asm("{ .reg .u64 t; cvta.to.shared.u64 t, %1; cvt.u32.u64 %0, t; }"
        : "=r"(a) : "l"(p));
    return a;
}
__device__ __forceinline__ void cp16(uint32_t dst, const void* src) {
    asm volatile("cp.async.cg.shared.global [%0], [%1], 16;"
                 :: "r"(dst), "l"(src));
}
__device__ __forceinline__ void cp_commit() {
    asm volatile("cp.async.commit_group;");
}
__device__ __forceinline__ void cp_wait1() {
    asm volatile("cp.async.wait_group 1;" ::: "memory");
}
__device__ __forceinline__ void cp_wait0() {
    asm volatile("cp.async.wait_group 0;" ::: "memory");
}
__device__ __forceinline__ void ldsm4(uint32_t* r, uint32_t addr) {
    asm volatile("ldmatrix.sync.aligned.m8n8.x4.shared.b16 {%0,%1,%2,%3}, [%4];"
                 : "=r"(r[0]), "=r"(r[1]), "=r"(r[2]), "=r"(r[3]) : "r"(addr));
}
__device__ __forceinline__ void ldsm4t(uint32_t* r, uint32_t addr) {
    asm volatile("ldmatrix.sync.aligned.m8n8.x4.trans.shared.b16 {%0,%1,%2,%3}, [%4];"
                 : "=r"(r[0]), "=r"(r[1]), "=r"(r[2]), "=r"(r[3]) : "r"(addr));
}
__device__ __forceinline__ void mma16816(float* c, const uint32_t* a, const uint32_t* b) {
    asm volatile(
        "mma.sync.aligned.m16n8k16.row.col.f32.bf16.bf16.f32 "
        "{%0,%1,%2,%3}, {%4,%5,%6,%7}, {%8,%9}, {%0,%1,%2,%3};"
        : "+f"(c[0]), "+f"(c[1]), "+f"(c[2]), "+f"(c[3])
        : "r"(a[0]), "r"(a[1]), "r"(a[2]), "r"(a[3]), "r"(b[0]), "r"(b[1]));
}
__device__ __forceinline__ void mma16816h(float* c, const uint32_t* a, const uint32_t* b) {
    asm volatile(
        "mma.sync.aligned.m16n8k16.row.col.f32.f16.f16.f32 "
        "{%0,%1,%2,%3}, {%4,%5,%6,%7}, {%8,%9}, {%0,%1,%2,%3};"
        : "+f"(c[0]), "+f"(c[1]), "+f"(c[2]), "+f"(c[3])
        : "r"(a[0]), "r"(a[1]), "r"(a[2]), "r"(a[3]), "r"(b[0]), "r"(b[1]));
}
// pack (lo, hi) floats -> bf16x2 (lo in low half)
__device__ __forceinline__ uint32_t packbf(float lo, float hi) {
    uint32_t r;
    asm("cvt.rn.bf16x2.f32 %0, %1, %2;" : "=r"(r) : "f"(hi), "f"(lo));
    return r;
}
// residual pack: (lo,hi) minus the bf16 values already packed in h
__device__ __forceinline__ uint32_t packlo(uint32_t h, float lo, float hi) {
    float hl = __int_as_float(h << 16);
    float hh = __int_as_float(h & 0xFFFF0000u);
    return packbf(lo - hl, hi - hh);
}
// pack (lo, hi) floats -> f16x2 (lo in low half)
__device__ __forceinline__ uint32_t packhf(float lo, float hi) {
    uint32_t r;
    asm("cvt.rn.f16x2.f32 %0, %1, %2;" : "=r"(r) : "f"(hi), "f"(lo));
    return r;
}
// fast 2^x on the FMA pipe (no MUFU). |err| ~ 2.4e-6 rel. x >= -126 clamped.
__device__ __forceinline__ float fexp2(float x) {
    x = fmaxf(x, -126.0f);
    float z = x + 12582912.0f;                 // round-to-nearest-int via magic
    int   n = __float_as_int(z) - 0x4B400000;
    float f = x - (z - 12582912.0f);           // f in [-0.5, 0.5]
    float p = 0.0013333558f;
    p = fmaf(p, f, 0.0096181291f);
    p = fmaf(p, f, 0.0555041087f);
    p = fmaf(p, f, 0.2402265070f);
    p = fmaf(p, f, 0.6931471806f);
    p = fmaf(p, f, 1.0f);
    return __int_as_float(__float_as_int(p) + (n << 23));
}

// ---------------------------------------------------------------------------
// fp16 GEMM: C[M,1024] = A[M,1024] @ W[1024,1024]^T (+bias)
// A fp16 single, W fp16 2-term split (2 MMA terms).
// mode 0: fp32 out.  mode 1: split bf16 out of (C+bias)*scale.  mode 2: fp16 out.
// CTA tile 128x128, 8 warps (4m x 2n), BK=64 double-buffered.
// ---------------------------------------------------------------------------
#define GBM 128
#define GBN 128
#define GBK 64
#define GNCH (ED / GBK)             // 16
#define TILE_B (GBM * GBK * 2)      // 16384 bytes
#define GO_A 0
#define GO_WH TILE_B
#define GO_WL (2 * TILE_B)
#define GO_BUF (3 * TILE_B)          // 49152
#define GEMMH_SMEM (2 * GO_BUF)      // 98304

__device__ __forceinline__ void h_load_chunk(
    uint32_t buf, int tid, int bm, int bn, int k0,
    const __half* __restrict__ A,
    const __half* __restrict__ Wh, const __half* __restrict__ Wl)
{
    #pragma unroll
    for (int i = 0; i < 4; i++) {
        int g   = tid + i * 256;
        int row = g >> 3, kg = g & 7;
        uint32_t so = (uint32_t)(row * 128 + ((kg ^ (row & 7)) << 4));
        size_t ga = (size_t)(bm + row) * ED + k0 + kg * 8;
        size_t gw = (size_t)(bn + row) * ED + k0 + kg * 8;
        cp16(buf + GO_A + so, A + ga);
        cp16(buf + GO_WH + so, Wh + gw);
        cp16(buf + GO_WL + so, Wl + gw);
    }
    cp_commit();
}

__global__ __launch_bounds__(256, 1) void gemm_h(
    const __half* __restrict__ A,
    const __half* __restrict__ Wh, const __half* __restrict__ Wl,
    const float* __restrict__ bias, float* __restrict__ C,
    __nv_bfloat16* __restrict__ Chi, __nv_bfloat16* __restrict__ Clo,
    __half* __restrict__ C16, float scale, int mode)
{
    const uint32_t sb = smem_u32(dyn_smem);
    const int tid  = threadIdx.x;
    const int wid  = tid >> 5, lane = tid & 31;
    const int wm   = wid & 3, wn = wid >> 2;
    const int m0   = wm * 32, n0 = wn * 64;
    const int bm   = blockIdx.y * GBM;
    const int bn   = blockIdx.x * GBN;

    float acc[2][8][4];
    #pragma unroll
    for (int a = 0; a < 2; a++)
        #pragma unroll
        for (int b = 0; b < 8; b++)
            #pragma unroll
            for (int c = 0; c < 4; c++) acc[a][b][c] = 0.0f;

    const int rowA_in = (lane & 15);
    const int khA     = lane >> 4;
    const int nrow_in = ((lane & 16) >> 1) + (lane & 7);
    const int khB     = (lane >> 3) & 1;

    h_load_chunk(sb, tid, bm, bn, 0, A, Wh, Wl);

    for (int ch = 0; ch < GNCH; ch++) {
        const uint32_t cur = sb + (uint32_t)(ch & 1) * GO_BUF;
        if (ch + 1 < GNCH) {
            h_load_chunk(sb + (uint32_t)((ch + 1) & 1) * GO_BUF, tid, bm, bn,
                         (ch + 1) * GBK, A, Wh, Wl);
            cp_wait1();
        } else {
            cp_wait0();
        }
        __syncthreads();

        #pragma unroll
        for (int k16 = 0; k16 < 4; k16++) {
            uint32_t ah[2][4];
            const int kgA = k16 * 2 + khA;
            #pragma unroll
            for (int mt = 0; mt < 2; mt++) {
                int rA = m0 + mt * 16 + rowA_in;
                uint32_t off = (uint32_t)(rA * 128 + ((kgA ^ (rA & 7)) << 4));
                ldsm4(ah[mt], cur + GO_A + off);
            }
            const int kgB = k16 * 2 + khB;
            #pragma unroll
            for (int g = 0; g < 4; g++) {
                int nr = n0 + g * 16 + nrow_in;
                uint32_t off = (uint32_t)(nr * 128 + ((kgB ^ (nr & 7)) << 4));
                uint32_t bh[4], bl[4];
                ldsm4(bh, cur + GO_WH + off);
                ldsm4(bl, cur + GO_WL + off);
                #pragma unroll
                for (int mt = 0; mt < 2; mt++) {
                    mma16816h(acc[mt][g * 2 + 0], ah[mt], &bh[0]);
                    mma16816h(acc[mt][g * 2 + 0], ah[mt], &bl[0]);
                    mma16816h(acc[mt][g * 2 + 1], ah[mt], &bh[2]);
                    mma16816h(acc[mt][g * 2 + 1], ah[mt], &bl[2]);
                }
            }
        }
        __syncthreads();
    }

    const int lr = lane >> 2;
    const int lc = (lane & 3) * 2;
    #pragma unroll
    for (int mt = 0; mt < 2; mt++) {
        #pragma unroll
        for (int nt = 0; nt < 8; nt++) {
            int row = bm + m0 + mt * 16 + lr;
            int col = bn + n0 + nt * 8 + lc;
            float2 b2 = *(const float2*)&bias[col];
            float vx = (acc[mt][nt][0] + b2.x) * scale;
            float vy = (acc[mt][nt][1] + b2.y) * scale;
            float wx = (acc[mt][nt][2] + b2.x) * scale;
            float wy = (acc[mt][nt][3] + b2.y) * scale;
            if (mode == 0) {
                *(float2*)&C[(size_t)row * ED + col]       = make_float2(vx, vy);
                *(float2*)&C[(size_t)(row + 8) * ED + col] = make_float2(wx, wy);
            } else if (mode == 1) {
                uint32_t h0 = packbf(vx, vy);
                uint32_t l0 = packlo(h0, vx, vy);
                uint32_t h1 = packbf(wx, wy);
                uint32_t l1 = packlo(h1, wx, wy);
                *(uint32_t*)&Chi[(size_t)row * ED + col]       = h0;
                *(uint32_t*)&Clo[(size_t)row * ED + col]       = l0;
                *(uint32_t*)&Chi[(size_t)(row + 8) * ED + col] = h1;
                *(uint32_t*)&Clo[(size_t)(row + 8) * ED + col] = l1;
            } else {
                *(uint32_t*)&C16[(size_t)row * ED + col]       = packhf(vx, vy);
                *(uint32_t*)&C16[(size_t)(row + 8) * ED + col] = packhf(wx, wy);
            }
        }
    }
}

// ---------------------------------------------------------------------------
// conversions
// ---------------------------------------------------------------------------
// fp32 -> fp16 single
__global__ void cast16_kernel(const float* __restrict__ x,
                              __half* __restrict__ y, int n4)
{
    int i = blockIdx.x * blockDim.x + threadIdx.x;
    if (i >= n4) return;
    float4 v = ((const float4*)x)[i];
    ((uint32_t*)y)[2 * i]     = packhf(v.x, v.y);
    ((uint32_t*)y)[2 * i + 1] = packhf(v.z, v.w);
}

// 4 weights -> fp16 hi/lo split in one launch
__global__ void wsplit16_kernel(const float* __restrict__ w0, const float* __restrict__ w1,
                                const float* __restrict__ w2, const float* __restrict__ w3,
                                __half* __restrict__ hi, __half* __restrict__ lo)
{
    int i = blockIdx.x * blockDim.x + threadIdx.x;   // float4 index over 4M elems
    if (i >= 4 * ED * ED / 4) return;
    int which = i >> 18;
    int off = i & 262143;
    const float* w = which == 0 ? w0 : which == 1 ? w1 : which == 2 ? w2 : w3;
    float4 v = ((const float4*)w)[off];
    __half h0 = __float2half(v.x), h1 = __float2half(v.y);
    __half h2 = __float2half(v.z), h3 = __float2half(v.w);
    __half l0 = __float2half(v.x - __half2float(h0));
    __half l1 = __float2half(v.y - __half2float(h1));
    __half l2 = __float2half(v.z - __half2float(h2));
    __half l3 = __float2half(v.w - __half2float(h3));
    ((__half2*)hi)[2 * i]     = __halves2half2(h0, h1);
    ((__half2*)hi)[2 * i + 1] = __halves2half2(h2, h3);
    ((__half2*)lo)[2 * i]     = __halves2half2(l0, l1);
    ((__half2*)lo)[2 * i + 1] = __halves2half2(l2, l3);
}

// log2 of multiplicities
__global__ void logm_kernel(const float* __restrict__ m, float* __restrict__ lm, int n)
{
    int i = blockIdx.x * blockDim.x + threadIdx.x;
    if (i < n) lm[i] = log2f(m[i]);
}

// ---------------------------------------------------------------------------
// HMMA flash attention (no-max softmax in log2 domain).
// QK^T: split bf16 3-term. PV: single fp16. Output: fp16 single.
// ---------------------------------------------------------------------------
#define AT_QH 0
#define AT_QL 16384
#define AT_BUF0 32768
#define AT_KH 0
#define AT_KL 16384
#define AT_V  32768
#define AT_LM 49152
#define AT_BUFB 49664                 // per double-buffer stride
#define ATTN_SMEM (AT_BUF0 + 2 * AT_BUFB)   // 132096

__device__ __forceinline__ void attn_load_tile(
    uint32_t buf, int tid, int b, int h, int k0,
    const __nv_bfloat16* __restrict__ Kh, const __nv_bfloat16* __restrict__ Kl,
    const __half* __restrict__ V,
    const float* __restrict__ lm)
{
    #pragma unroll
    for (int i = 0; i < 4; i++) {
        int g   = tid + i * 256;        // 0..1023
        int row = g >> 3, kg = g & 7;
        uint32_t so = (uint32_t)(row * 128 + ((kg ^ (row & 7)) << 4));
        size_t gk = (size_t)(b * NKL + k0 + row) * ED + h * HD + kg * 8;
        cp16(buf + AT_KH + so, Kh + gk);
        cp16(buf + AT_KL + so, Kl + gk);
        cp16(buf + AT_V  + so, V + gk);
    }
    if (tid < 32)
        cp16(buf + AT_LM + tid * 16, lm + b * NKL + k0 + tid * 4);
    cp_commit();
}

__global__ __launch_bounds__(256, 1) void attn_mma(
    const __nv_bfloat16* __restrict__ Qh, const __nv_bfloat16* __restrict__ Ql,
    const __nv_bfloat16* __restrict__ Kh, const __nv_bfloat16* __restrict__ Kl,
    const __half* __restrict__ V,
    const float* __restrict__ logm,
    __half* __restrict__ O16)
{
    const uint32_t sb = smem_u32(dyn_smem);
    const int tid  = threadIdx.x;
    const int wid  = tid >> 5, lane = tid & 31;
    const int qt = blockIdx.x, h = blockIdx.y, b = blockIdx.z;
    const int q0 = qt * 128;
    const int m0 = wid * 16;

    const int rowA_in = (lane & 15);
    const int khA     = lane >> 4;
    const int nrow_in = ((lane & 16) >> 1) + (lane & 7);
    const int khB     = (lane >> 3) & 1;

    // Q tile load (q-rows 0..127, 64 d) hi/lo
    #pragma unroll
    for (int i = 0; i < 4; i++) {
        int g   = tid + i * 256;
        int row = g >> 3, kg = g & 7;
        uint32_t so = (uint32_t)(row * 128 + ((kg ^ (row & 7)) << 4));
        size_t gq = (size_t)(b * NQL + q0 + row) * ED + h * HD + kg * 8;
        cp16(sb + AT_QH + so, Qh + gq);
        cp16(sb + AT_QL + so, Ql + gq);
    }
    cp_commit();
    attn_load_tile(sb + AT_BUF0, tid, b, h, 0, Kh, Kl, V, logm);

    float oacc[8][4];
    #pragma unroll
    for (int j = 0; j < 8; j++)
        #pragma unroll
        for (int c = 0; c < 4; c++) oacc[j][c] = 0.0f;
    float lsum0 = 0.0f, lsum1 = 0.0f;

    const int NT = NKL / 128;   // 16
    for (int t = 0; t < NT; t++) {
        const uint32_t cur = sb + AT_BUF0 + (uint32_t)(t & 1) * AT_BUFB;
        if (t + 1 < NT) {
            attn_load_tile(sb + AT_BUF0 + (uint32_t)((t + 1) & 1) * AT_BUFB,
                           tid, b, h, (t + 1) * 128, Kh, Kl, V, logm);
            cp_wait1();
        } else {
            cp_wait0();
        }
        __syncthreads();

        // ---- S = Q K^T (split bf16, 3 terms)
        float s[16][4];
        #pragma unroll
        for (int j = 0; j < 16; j++)
            #pragma unroll
            for (int c = 0; c < 4; c++) s[j][c] = 0.0f;

        #pragma unroll
        for (int k16 = 0; k16 < 4; k16++) {
            uint32_t qah[4], qal[4];
            const int kgA = k16 * 2 + khA;
            {
                int rA = m0 + rowA_in;
                uint32_t off = (uint32_t)(rA * 128 + ((kgA ^ (rA & 7)) << 4));
                ldsm4(qah, sb + AT_QH + off);
                ldsm4(qal, sb + AT_QL + off);
            }
            const int kgB = k16 * 2 + khB;
            #pragma unroll
            for (int g = 0; g < 8; g++) {
                int nr = g * 16 + nrow_in;
                uint32_t off = (uint32_t)(nr * 128 + ((kgB ^ (nr & 7)) << 4));
                uint32_t bh[4], bl[4];
                ldsm4(bh, cur + AT_KH + off);
                ldsm4(bl, cur + AT_KL + off);
                mma16816(s[g * 2 + 0], qah, &bh[0]);
                mma16816(s[g * 2 + 0], qah, &bl[0]);
                mma16816(s[g * 2 + 0], qal, &bh[0]);
                mma16816(s[g * 2 + 1], qah, &bh[2]);
                mma16816(s[g * 2 + 1], qah, &bl[2]);
                mma16816(s[g * 2 + 1], qal, &bh[2]);
            }
        }

        // ---- p = 2^(s + log2 m), accumulate row sums
        const float* LmS = (const float*)(dyn_smem +
            (AT_BUF0 + (size_t)(t & 1) * AT_BUFB + AT_LM));
        #pragma unroll
        for (int j = 0; j < 16; j++) {
            float2 l2 = *(const float2*)&LmS[8 * j + (lane & 3) * 2];
            s[j][0] = fexp2(s[j][0] + l2.x);
            s[j][1] = fexp2(s[j][1] + l2.y);
            s[j][2] = fexp2(s[j][2] + l2.x);
            s[j][3] = fexp2(s[j][3] + l2.y);
            lsum0 += s[j][0] + s[j][1];
            lsum1 += s[j][2] + s[j][3];
        }

        // ---- O += P V (single fp16 term). P fragments built in-register.
        #pragma unroll
        for (int kt = 0; kt < 8; kt++) {
            uint32_t aph[4];
            aph[0] = packhf(s[2 * kt][0],     s[2 * kt][1]);
            aph[1] = packhf(s[2 * kt][2],     s[2 * kt][3]);
            aph[2] = packhf(s[2 * kt + 1][0], s[2 * kt + 1][1]);
            aph[3] = packhf(s[2 * kt + 1][2], s[2 * kt + 1][3]);

            #pragma unroll
            for (int j = 0; j < 4; j++) {   // d-chunk pairs (16 d per iter)
                int row = kt * 16 + (lane & 15);
                int ck  = 2 * j + (lane >> 4);
                uint32_t off = (uint32_t)(row * 128 + ((ck ^ (row & 7)) << 4));
                uint32_t vhf[4];
                ldsm4t(vhf, cur + AT_V + off);
                mma16816h(oacc[2 * j + 0], aph, &vhf[0]);
                mma16816h(oacc[2 * j + 1], aph, &vhf[2]);
            }
        }
        __syncthreads();
    }

    // ---- reduce row sums over the 4 lanes of each row quad
    #pragma unroll
    for (int off = 1; off <= 2; off <<= 1) {
        lsum0 += __shfl_xor_sync(0xffffffffu, lsum0, off);
        lsum1 += __shfl_xor_sync(0xffffffffu, lsum1, off);
    }
    const float inv0 = 1.0f / lsum0;
    const float inv1 = 1.0f / lsum1;

    // ---- normalize + fp16 write to [b, q, h*64 + d]
    const int row0 = q0 + m0 + (lane >> 2);
    const int col0 = h * HD + (lane & 3) * 2;
    #pragma unroll
    for (int j = 0; j < 8; j++) {
        int col = col0 + 8 * j;
        *(uint32_t*)&O16[(size_t)(b * NQL + row0) * ED + col] =
            packhf(oacc[j][0] * inv0, oacc[j][1] * inv0);
        *(uint32_t*)&O16[(size_t)(b * NQL + row0 + 8) * ED + col] =
            packhf(oacc[j][2] * inv1, oacc[j][3] * inv1);
    }
}

// ---------------------------------------------------------------------------
extern "C" void kernel_launch(void* const* d_in, const int* in_sizes, int n_in,
                              void* d_out, int out_size)
{
    const float* query = (const float*)d_in[0];
    const float* key   = (const float*)d_in[1];
    const float* value = (const float*)d_in[2];
    const float* kmult = (const float*)d_in[3];
    const float* wq_w  = (const float*)d_in[4];
    const float* wq_b  = (const float*)d_in[5];
    const float* wk_w  = (const float*)d_in[6];
    const float* wk_b  = (const float*)d_in[7];
    const float* wv_w  = (const float*)d_in[8];
    const float* wv_b  = (const float*)d_in[9];
    const float* wo_w  = (const float*)d_in[10];
    const float* wo_b  = (const float*)d_in[11];
    float* out = (float*)d_out;

    float* lm;
    cudaGetSymbolAddress((void**)&lm, g_logm);
    __nv_bfloat16 *pqh, *pql, *pkh, *pkl;
    __half *xq16, *xk16, *xv16, *pv16, *ao16, *w16h, *w16l;
    cudaGetSymbolAddress((void**)&xq16, g_xq16);
    cudaGetSymbolAddress((void**)&xk16, g_xk16);
    cudaGetSymbolAddress((void**)&xv16, g_xv16);
    cudaGetSymbolAddress((void**)&w16h, g_w16h);
    cudaGetSymbolAddress((void**)&w16l, g_w16l);
    cudaGetSymbolAddress((void**)&pqh, g_pq_h);
    cudaGetSymbolAddress((void**)&pql, g_pq_l);
    cudaGetSymbolAddress((void**)&pkh, g_pk_h);
    cudaGetSymbolAddress((void**)&pkl, g_pk_l);
    cudaGetSymbolAddress((void**)&pv16, g_pv16);
    cudaGetSymbolAddress((void**)&ao16, g_ao16);

    cudaFuncSetAttribute(gemm_h,
                         cudaFuncAttributeMaxDynamicSharedMemorySize, GEMMH_SMEM);
    cudaFuncSetAttribute(attn_mma,
                         cudaFuncAttributeMaxDynamicSharedMemorySize, ATTN_SMEM);

    const int NQ4 = BB * NQL * ED / 4;
    const int NK4 = BB * NKL * ED / 4;
    const float QSCALE = 0.18033688011112042f;   // log2(e)/8

    // input conversions + log2(multiplicities)
    cast16_kernel<<<(NQ4 + 255) / 256, 256>>>(query, xq16, NQ4);
    cast16_kernel<<<(NK4 + 255) / 256, 256>>>(key,   xk16, NK4);
    cast16_kernel<<<(NK4 + 255) / 256, 256>>>(value, xv16, NK4);
    wsplit16_kernel<<<(4 * ED * ED / 4 + 255) / 256, 256>>>(
        wq_w, wk_w, wv_w, wo_w, w16h, w16l);
    logm_kernel<<<(BB * NKL + 255) / 256, 256>>>(kmult, lm, BB * NKL);

    // projections: all fp16-A x fp16-2-term-W
    {
        dim3 blk(256);
        dim3 gq(ED / GBN, (BB * NQL) / GBM);   // (8, 32)
        dim3 gk(ED / GBN, (BB * NKL) / GBM);   // (8, 64)
        // Q -> split bf16, pre-scaled by log2(e)/8
        gemm_h<<<gq, blk, GEMMH_SMEM>>>(xq16, w16h + 0 * ED * ED, w16l + 0 * ED * ED,
                                        wq_b, nullptr, pqh, pql, nullptr, QSCALE, 1);
        // K -> split bf16
        gemm_h<<<gk, blk, GEMMH_SMEM>>>(xk16, w16h + 1 * ED * ED, w16l + 1 * ED * ED,
                                        wk_b, nullptr, pkh, pkl, nullptr, 1.0f, 1);
        // V -> fp16 single
        gemm_h<<<gk, blk, GEMMH_SMEM>>>(xv16, w16h + 2 * ED * ED, w16l + 2 * ED * ED,
                                        wv_b, nullptr, nullptr, nullptr, pv16, 1.0f, 2);
    }

    // attention (QK split bf16, PV single fp16) -> fp16 O
    {
        dim3 grid(NQL / 128, NH, BB);
        attn_mma<<<grid, 256, ATTN_SMEM>>>(pqh, pql, pkh, pkl, pv16, lm, ao16);
    }

    // output projection -> fp32 out
    {
        dim3 blk(256);
        dim3 go(ED / GBN, (BB * NQL) / GBM);
        gemm_h<<<go, blk, GEMMH_SMEM>>>(ao16, w16h + 3 * ED * ED, w16l + 3 * ED * ED,
                                        wo_b, out, nullptr, nullptr, nullptr, 1.0f, 0);
    }
}

// round 14
// speedup vs baseline: 4.6616x; 1.0665x over previous
#include <cuda_runtime.h>
#include <cuda_bf16.h>
#include <cuda_fp16.h>
#include <math.h>
#include <stdint.h>

#define BB 4
#define NH 16
#define HD 64
#define ED 1024
#define NQL 1024
#define NKL 2048

// ---------------------------------------------------------------------------
// Scratch (no cudaMalloc allowed)
// ---------------------------------------------------------------------------
__device__ float g_logm[BB * NKL];        // log2 multiplicities

// conversion outputs
__device__ __half g_xq16[BB * NQL * ED];              // query fp16
__device__ __half g_xk16[BB * NKL * ED];              // key fp16
__device__ __half g_xv16[BB * NKL * ED];              // value fp16
__device__ __half g_w16h[4 * ED * ED], g_w16l[4 * ED * ED];  // wq,wk,wv,wo fp16 split

// projected outputs (all fp16 single)
__device__ __half g_pq16[BB * NQL * ED];
__device__ __half g_pk16[BB * NKL * ED];
__device__ __half g_pv16[BB * NKL * ED];
__device__ __half g_ao16[BB * NQL * ED];

// single dynamic-smem symbol for the whole TU
extern __shared__ char dyn_smem[];

// ---------------------------------------------------------------------------
// helpers
// ---------------------------------------------------------------------------
__device__ __forceinline__ uint32_t smem_u32(const void* p) {
    uint32_t a;
    asm("{ .reg .u64 t; cvta.to.shared.u64 t, %1; cvt.u32.u64 %0, t; }"
        : "=r"(a) : "l"(p));
    return a;
}
__device__ __forceinline__ void cp16(uint32_t dst, const void* src) {
    asm volatile("cp.async.cg.shared.global [%0], [%1], 16;"
                 :: "r"(dst), "l"(src));
}
__device__ __forceinline__ void cp_commit() {
    asm volatile("cp.async.commit_group;");
}
__device__ __forceinline__ void cp_wait1() {
    asm volatile("cp.async.wait_group 1;" ::: "memory");
}
__device__ __forceinline__ void cp_wait0() {
    asm volatile("cp.async.wait_group 0;" ::: "memory");
}
__device__ __forceinline__ void ldsm4(uint32_t* r, uint32_t addr) {
    asm volatile("ldmatrix.sync.aligned.m8n8.x4.shared.b16 {%0,%1,%2,%3}, [%4];"
                 : "=r"(r[0]), "=r"(r[1]), "=r"(r[2]), "=r"(r[3]) : "r"(addr));
}
__device__ __forceinline__ void ldsm4t(uint32_t* r, uint32_t addr) {
    asm volatile("ldmatrix.sync.aligned.m8n8.x4.trans.shared.b16 {%0,%1,%2,%3}, [%4];"
                 : "=r"(r[0]), "=r"(r[1]), "=r"(r[2]), "=r"(r[3]) : "r"(addr));
}
__device__ __forceinline__ void mma16816h(float* c, const uint32_t* a, const uint32_t* b) {
    asm volatile(
        "mma.sync.aligned.m16n8k16.row.col.f32.f16.f16.f32 "
        "{%0,%1,%2,%3}, {%4,%5,%6,%7}, {%8,%9}, {%0,%1,%2,%3};"
        : "+f"(c[0]), "+f"(c[1]), "+f"(c[2]), "+f"(c[3])
        : "r"(a[0]), "r"(a[1]), "r"(a[2]), "r"(a[3]), "r"(b[0]), "r"(b[1]));
}
// pack (lo, hi) floats -> f16x2 (lo in low half)
__device__ __forceinline__ uint32_t packhf(float lo, float hi) {
    uint32_t r;
    asm("cvt.rn.f16x2.f32 %0, %1, %2;" : "=r"(r) : "f"(hi), "f"(lo));
    return r;
}
// fast 2^x on the FMA pipe (no MUFU). |err| ~ 2.4e-6 rel. x >= -126 clamped.
__device__ __forceinline__ float fexp2(float x) {
    x = fmaxf(x, -126.0f);
    float z = x + 12582912.0f;                 // round-to-nearest-int via magic
    int   n = __float_as_int(z) - 0x4B400000;
    float f = x - (z - 12582912.0f);           // f in [-0.5, 0.5]
    float p = 0.0013333558f;
    p = fmaf(p, f, 0.0096181291f);
    p = fmaf(p, f, 0.0555041087f);
    p = fmaf(p, f, 0.2402265070f);
    p = fmaf(p, f, 0.6931471806f);
    p = fmaf(p, f, 1.0f);
    return __int_as_float(__float_as_int(p) + (n << 23));
}

// ---------------------------------------------------------------------------
// fp16 GEMM: C[M,1024] = A[M,1024] @ W[1024,1024]^T (+bias)
// A fp16 single, W fp16 2-term split (2 MMA terms).
// mode 0: fp32 out.  mode 2: fp16 out of (C+bias)*scale.
// CTA tile 128x128, 8 warps (4m x 2n), BK=64 double-buffered.
// ---------------------------------------------------------------------------
#define GBM 128
#define GBN 128
#define GBK 64
#define GNCH (ED / GBK)             // 16
#define TILE_B (GBM * GBK * 2)      // 16384 bytes
#define GO_A 0
#define GO_WH TILE_B
#define GO_WL (2 * TILE_B)
#define GO_BUF (3 * TILE_B)          // 49152
#define GEMMH_SMEM (2 * GO_BUF)      // 98304

__device__ __forceinline__ void h_load_chunk(
    uint32_t buf, int tid, int bm, int bn, int k0,
    const __half* __restrict__ A,
    const __half* __restrict__ Wh, const __half* __restrict__ Wl)
{
    #pragma unroll
    for (int i = 0; i < 4; i++) {
        int g   = tid + i * 256;
        int row = g >> 3, kg = g & 7;
        uint32_t so = (uint32_t)(row * 128 + ((kg ^ (row & 7)) << 4));
        size_t ga = (size_t)(bm + row) * ED + k0 + kg * 8;
        size_t gw = (size_t)(bn + row) * ED + k0 + kg * 8;
        cp16(buf + GO_A + so, A + ga);
        cp16(buf + GO_WH + so, Wh + gw);
        cp16(buf + GO_WL + so, Wl + gw);
    }
    cp_commit();
}

__global__ __launch_bounds__(256, 1) void gemm_h(
    const __half* __restrict__ A,
    const __half* __restrict__ Wh, const __half* __restrict__ Wl,
    const float* __restrict__ bias, float* __restrict__ C,
    __half* __restrict__ C16, float scale, int mode)
{
    const uint32_t sb = smem_u32(dyn_smem);
    const int tid  = threadIdx.x;
    const int wid  = tid >> 5, lane = tid & 31;
    const int wm   = wid & 3, wn = wid >> 2;
    const int m0   = wm * 32, n0 = wn * 64;
    const int bm   = blockIdx.y * GBM;
    const int bn   = blockIdx.x * GBN;

    float acc[2][8][4];
    #pragma unroll
    for (int a = 0; a < 2; a++)
        #pragma unroll
        for (int b = 0; b < 8; b++)
            #pragma unroll
            for (int c = 0; c < 4; c++) acc[a][b][c] = 0.0f;

    const int rowA_in = (lane & 15);
    const int khA     = lane >> 4;
    const int nrow_in = ((lane & 16) >> 1) + (lane & 7);
    const int khB     = (lane >> 3) & 1;

    h_load_chunk(sb, tid, bm, bn, 0, A, Wh, Wl);

    for (int ch = 0; ch < GNCH; ch++) {
        const uint32_t cur = sb + (uint32_t)(ch & 1) * GO_BUF;
        if (ch + 1 < GNCH) {
            h_load_chunk(sb + (uint32_t)((ch + 1) & 1) * GO_BUF, tid, bm, bn,
                         (ch + 1) * GBK, A, Wh, Wl);
            cp_wait1();
        } else {
            cp_wait0();
        }
        __syncthreads();

        #pragma unroll
        for (int k16 = 0; k16 < 4; k16++) {
            uint32_t ah[2][4];
            const int kgA = k16 * 2 + khA;
            #pragma unroll
            for (int mt = 0; mt < 2; mt++) {
                int rA = m0 + mt * 16 + rowA_in;
                uint32_t off = (uint32_t)(rA * 128 + ((kgA ^ (rA & 7)) << 4));
                ldsm4(ah[mt], cur + GO_A + off);
            }
            const int kgB = k16 * 2 + khB;
            #pragma unroll
            for (int g = 0; g < 4; g++) {
                int nr = n0 + g * 16 + nrow_in;
                uint32_t off = (uint32_t)(nr * 128 + ((kgB ^ (nr & 7)) << 4));
                uint32_t bh[4], bl[4];
                ldsm4(bh, cur + GO_WH + off);
                ldsm4(bl, cur + GO_WL + off);
                #pragma unroll
                for (int mt = 0; mt < 2; mt++) {
                    mma16816h(acc[mt][g * 2 + 0], ah[mt], &bh[0]);
                    mma16816h(acc[mt][g * 2 + 0], ah[mt], &bl[0]);
                    mma16816h(acc[mt][g * 2 + 1], ah[mt], &bh[2]);
                    mma16816h(acc[mt][g * 2 + 1], ah[mt], &bl[2]);
                }
            }
        }
        __syncthreads();
    }

    const int lr = lane >> 2;
    const int lc = (lane & 3) * 2;
    #pragma unroll
    for (int mt = 0; mt < 2; mt++) {
        #pragma unroll
        for (int nt = 0; nt < 8; nt++) {
            int row = bm + m0 + mt * 16 + lr;
            int col = bn + n0 + nt * 8 + lc;
            float2 b2 = *(const float2*)&bias[col];
            float vx = (acc[mt][nt][0] + b2.x) * scale;
            float vy = (acc[mt][nt][1] + b2.y) * scale;
            float wx = (acc[mt][nt][2] + b2.x) * scale;
            float wy = (acc[mt][nt][3] + b2.y) * scale;
            if (mode == 0) {
                *(float2*)&C[(size_t)row * ED + col]       = make_float2(vx, vy);
                *(float2*)&C[(size_t)(row + 8) * ED + col] = make_float2(wx, wy);
            } else {
                *(uint32_t*)&C16[(size_t)row * ED + col]       = packhf(vx, vy);
                *(uint32_t*)&C16[(size_t)(row + 8) * ED + col] = packhf(wx, wy);
            }
        }
    }
}

// ---------------------------------------------------------------------------
// conversions
// ---------------------------------------------------------------------------
// all three inputs -> fp16 in one launch
#define NQ4C (BB * NQL * ED / 4)    // 1048576
#define NK4C (BB * NKL * ED / 4)    // 2097152
__global__ void cast16_all(const float* __restrict__ q, const float* __restrict__ k,
                           const float* __restrict__ v,
                           __half* __restrict__ yq, __half* __restrict__ yk,
                           __half* __restrict__ yv)
{
    int i = blockIdx.x * blockDim.x + threadIdx.x;   // 0 .. 5M-1
    const float* x;
    __half* y;
    int off;
    if (i < NQ4C) { x = q; y = yq; off = i; }
    else if (i < NQ4C + NK4C) { x = k; y = yk; off = i - NQ4C; }
    else if (i < NQ4C + 2 * NK4C) { x = v; y = yv; off = i - NQ4C - NK4C; }
    else return;
    float4 val = ((const float4*)x)[off];
    ((uint32_t*)y)[2 * off]     = packhf(val.x, val.y);
    ((uint32_t*)y)[2 * off + 1] = packhf(val.z, val.w);
}

// 4 weights -> fp16 hi/lo split in one launch
__global__ void wsplit16_kernel(const float* __restrict__ w0, const float* __restrict__ w1,
                                const float* __restrict__ w2, const float* __restrict__ w3,
                                __half* __restrict__ hi, __half* __restrict__ lo)
{
    int i = blockIdx.x * blockDim.x + threadIdx.x;   // float4 index over 4M elems
    if (i >= 4 * ED * ED / 4) return;
    int which = i >> 18;
    int off = i & 262143;
    const float* w = which == 0 ? w0 : which == 1 ? w1 : which == 2 ? w2 : w3;
    float4 v = ((const float4*)w)[off];
    __half h0 = __float2half(v.x), h1 = __float2half(v.y);
    __half h2 = __float2half(v.z), h3 = __float2half(v.w);
    __half l0 = __float2half(v.x - __half2float(h0));
    __half l1 = __float2half(v.y - __half2float(h1));
    __half l2 = __float2half(v.z - __half2float(h2));
    __half l3 = __float2half(v.w - __half2float(h3));
    ((__half2*)hi)[2 * i]     = __halves2half2(h0, h1);
    ((__half2*)hi)[2 * i + 1] = __halves2half2(h2, h3);
    ((__half2*)lo)[2 * i]     = __halves2half2(l0, l1);
    ((__half2*)lo)[2 * i + 1] = __halves2half2(l2, l3);
}

// log2 of multiplicities
__global__ void logm_kernel(const float* __restrict__ m, float* __restrict__ lm, int n)
{
    int i = blockIdx.x * blockDim.x + threadIdx.x;
    if (i < n) lm[i] = log2f(m[i]);
}

// ---------------------------------------------------------------------------
// HMMA flash attention, fully fp16 (no-max softmax in log2 domain).
// QK^T: single fp16 term. PV: single fp16. Output: fp16 single.
// ---------------------------------------------------------------------------
#define AT_Q 0
#define AT_BUF0 16384
#define AT_K 0
#define AT_V 16384
#define AT_LM 32768
#define AT_BUFB 33280                 // per double-buffer stride
#define ATTN_SMEM (AT_BUF0 + 2 * AT_BUFB)   // 82944

__device__ __forceinline__ void attn_load_tile(
    uint32_t buf, int tid, int b, int h, int k0,
    const __half* __restrict__ K, const __half* __restrict__ V,
    const float* __restrict__ lm)
{
    #pragma unroll
    for (int i = 0; i < 4; i++) {
        int g   = tid + i * 256;        // 0..1023
        int row = g >> 3, kg = g & 7;
        uint32_t so = (uint32_t)(row * 128 + ((kg ^ (row & 7)) << 4));
        size_t gk = (size_t)(b * NKL + k0 + row) * ED + h * HD + kg * 8;
        cp16(buf + AT_K + so, K + gk);
        cp16(buf + AT_V + so, V + gk);
    }
    if (tid < 32)
        cp16(buf + AT_LM + tid * 16, lm + b * NKL + k0 + tid * 4);
    cp_commit();
}

__global__ __launch_bounds__(256, 1) void attn_mma(
    const __half* __restrict__ Q, const __half* __restrict__ K,
    const __half* __restrict__ V,
    const float* __restrict__ logm,
    __half* __restrict__ O16)
{
    const uint32_t sb = smem_u32(dyn_smem);
    const int tid  = threadIdx.x;
    const int wid  = tid >> 5, lane = tid & 31;
    const int qt = blockIdx.x, h = blockIdx.y, b = blockIdx.z;
    const int q0 = qt * 128;
    const int m0 = wid * 16;

    const int rowA_in = (lane & 15);
    const int khA     = lane >> 4;
    const int nrow_in = ((lane & 16) >> 1) + (lane & 7);
    const int khB     = (lane >> 3) & 1;

    // Q tile load (q-rows 0..127, 64 d) fp16
    #pragma unroll
    for (int i = 0; i < 2; i++) {
        int g   = tid + i * 256;        // 0..511
        int row = g >> 2, kg = (g & 3) * 2;   // two 16B groups per thread-slot
        uint32_t so = (uint32_t)(row * 128 + ((kg ^ (row & 7)) << 4));
        uint32_t so2 = (uint32_t)(row * 128 + (((kg + 1) ^ (row & 7)) << 4));
        size_t gq = (size_t)(b * NQL + q0 + row) * ED + h * HD + kg * 8;
        cp16(sb + AT_Q + so,  Q + gq);
        cp16(sb + AT_Q + so2, Q + gq + 8);
    }
    cp_commit();
    attn_load_tile(sb + AT_BUF0, tid, b, h, 0, K, V, logm);

    float oacc[8][4];
    #pragma unroll
    for (int j = 0; j < 8; j++)
        #pragma unroll
        for (int c = 0; c < 4; c++) oacc[j][c] = 0.0f;
    float lsum0 = 0.0f, lsum1 = 0.0f;

    const int NT = NKL / 128;   // 16
    for (int t = 0; t < NT; t++) {
        const uint32_t cur = sb + AT_BUF0 + (uint32_t)(t & 1) * AT_BUFB;
        if (t + 1 < NT) {
            attn_load_tile(sb + AT_BUF0 + (uint32_t)((t + 1) & 1) * AT_BUFB,
                           tid, b, h, (t + 1) * 128, K, V, logm);
            cp_wait1();
        } else {
            cp_wait0();
        }
        __syncthreads();

        // ---- S = Q K^T (single fp16 term)
        float s[16][4];
        #pragma unroll
        for (int j = 0; j < 16; j++)
            #pragma unroll
            for (int c = 0; c < 4; c++) s[j][c] = 0.0f;

        #pragma unroll
        for (int k16 = 0; k16 < 4; k16++) {
            uint32_t qah[4];
            const int kgA = k16 * 2 + khA;
            {
                int rA = m0 + rowA_in;
                uint32_t off = (uint32_t)(rA * 128 + ((kgA ^ (rA & 7)) << 4));
                ldsm4(qah, sb + AT_Q + off);
            }
            const int kgB = k16 * 2 + khB;
            #pragma unroll
            for (int g = 0; g < 8; g++) {
                int nr = g * 16 + nrow_in;
                uint32_t off = (uint32_t)(nr * 128 + ((kgB ^ (nr & 7)) << 4));
                uint32_t bh[4];
                ldsm4(bh, cur + AT_K + off);
                mma16816h(s[g * 2 + 0], qah, &bh[0]);
                mma16816h(s[g * 2 + 1], qah, &bh[2]);
            }
        }

        // ---- p = 2^(s + log2 m), accumulate row sums
        const float* LmS = (const float*)(dyn_smem +
            (AT_BUF0 + (size_t)(t & 1) * AT_BUFB + AT_LM));
        #pragma unroll
        for (int j = 0; j < 16; j++) {
            float2 l2 = *(const float2*)&LmS[8 * j + (lane & 3) * 2];
            s[j][0] = fexp2(s[j][0] + l2.x);
            s[j][1] = fexp2(s[j][1] + l2.y);
            s[j][2] = fexp2(s[j][2] + l2.x);
            s[j][3] = fexp2(s[j][3] + l2.y);
            lsum0 += s[j][0] + s[j][1];
            lsum1 += s[j][2] + s[j][3];
        }

        // ---- O += P V (single fp16 term). P fragments built in-register.
        #pragma unroll
        for (int kt = 0; kt < 8; kt++) {
            uint32_t aph[4];
            aph[0] = packhf(s[2 * kt][0],     s[2 * kt][1]);
            aph[1] = packhf(s[2 * kt][2],     s[2 * kt][3]);
            aph[2] = packhf(s[2 * kt + 1][0], s[2 * kt + 1][1]);
            aph[3] = packhf(s[2 * kt + 1][2], s[2 * kt + 1][3]);

            #pragma unroll
            for (int j = 0; j < 4; j++) {   // d-chunk pairs (16 d per iter)
                int row = kt * 16 + (lane & 15);
                int ck  = 2 * j + (lane >> 4);
                uint32_t off = (uint32_t)(row * 128 + ((ck ^ (row & 7)) << 4));
                uint32_t vhf[4];
                ldsm4t(vhf, cur + AT_V + off);
                mma16816h(oacc[2 * j + 0], aph, &vhf[0]);
                mma16816h(oacc[2 * j + 1], aph, &vhf[2]);
            }
        }
        __syncthreads();
    }

    // ---- reduce row sums over the 4 lanes of each row quad
    #pragma unroll
    for (int off = 1; off <= 2; off <<= 1) {
        lsum0 += __shfl_xor_sync(0xffffffffu, lsum0, off);
        lsum1 += __shfl_xor_sync(0xffffffffu, lsum1, off);
    }
    const float inv0 = 1.0f / lsum0;
    const float inv1 = 1.0f / lsum1;

    // ---- normalize + fp16 write to [b, q, h*64 + d]
    const int row0 = q0 + m0 + (lane >> 2);
    const int col0 = h * HD + (lane & 3) * 2;
    #pragma unroll
    for (int j = 0; j < 8; j++) {
        int col = col0 + 8 * j;
        *(uint32_t*)&O16[(size_t)(b * NQL + row0) * ED + col] =
            packhf(oacc[j][0] * inv0, oacc[j][1] * inv0);
        *(uint32_t*)&O16[(size_t)(b * NQL + row0 + 8) * ED + col] =
            packhf(oacc[j][2] * inv1, oacc[j][3] * inv1);
    }
}

// ---------------------------------------------------------------------------
extern "C" void kernel_launch(void* const* d_in, const int* in_sizes, int n_in,
                              void* d_out, int out_size)
{
    const float* query = (const float*)d_in[0];
    const float* key   = (const float*)d_in[1];
    const float* value = (const float*)d_in[2];
    const float* kmult = (const float*)d_in[3];
    const float* wq_w  = (const float*)d_in[4];
    const float* wq_b  = (const float*)d_in[5];
    const float* wk_w  = (const float*)d_in[6];
    const float* wk_b  = (const float*)d_in[7];
    const float* wv_w  = (const float*)d_in[8];
    const float* wv_b  = (const float*)d_in[9];
    const float* wo_w  = (const float*)d_in[10];
    const float* wo_b  = (const float*)d_in[11];
    float* out = (float*)d_out;

    float* lm;
    cudaGetSymbolAddress((void**)&lm, g_logm);
    __half *xq16, *xk16, *xv16, *pq16, *pk16, *pv16, *ao16, *w16h, *w16l;
    cudaGetSymbolAddress((void**)&xq16, g_xq16);
    cudaGetSymbolAddress((void**)&xk16, g_xk16);
    cudaGetSymbolAddress((void**)&xv16, g_xv16);
    cudaGetSymbolAddress((void**)&w16h, g_w16h);
    cudaGetSymbolAddress((void**)&w16l, g_w16l);
    cudaGetSymbolAddress((void**)&pq16, g_pq16);
    cudaGetSymbolAddress((void**)&pk16, g_pk16);
    cudaGetSymbolAddress((void**)&pv16, g_pv16);
    cudaGetSymbolAddress((void**)&ao16, g_ao16);

    cudaFuncSetAttribute(gemm_h,
                         cudaFuncAttributeMaxDynamicSharedMemorySize, GEMMH_SMEM);
    cudaFuncSetAttribute(attn_mma,
                         cudaFuncAttributeMaxDynamicSharedMemorySize, ATTN_SMEM);

    const float QSCALE = 0.18033688011112042f;   // log2(e)/8

    // input conversions + log2(multiplicities)
    {
        int total = NQ4C + 2 * NK4C;    // 5M float4s
        cast16_all<<<(total + 255) / 256, 256>>>(query, key, value, xq16, xk16, xv16);
    }
    wsplit16_kernel<<<(4 * ED * ED / 4 + 255) / 256, 256>>>(
        wq_w, wk_w, wv_w, wo_w, w16h, w16l);
    logm_kernel<<<(BB * NKL + 255) / 256, 256>>>(kmult, lm, BB * NKL);

    // projections: all fp16-A x fp16-2-term-W -> fp16 single outputs
    {
        dim3 blk(256);
        dim3 gq(ED / GBN, (BB * NQL) / GBM);   // (8, 32)
        dim3 gk(ED / GBN, (BB * NKL) / GBM);   // (8, 64)
        // Q pre-scaled by log2(e)/8
        gemm_h<<<gq, blk, GEMMH_SMEM>>>(xq16, w16h + 0 * ED * ED, w16l + 0 * ED * ED,
                                        wq_b, nullptr, pq16, QSCALE, 2);
        gemm_h<<<gk, blk, GEMMH_SMEM>>>(xk16, w16h + 1 * ED * ED, w16l + 1 * ED * ED,
                                        wk_b, nullptr, pk16, 1.0f, 2);
        gemm_h<<<gk, blk, GEMMH_SMEM>>>(xv16, w16h + 2 * ED * ED, w16l + 2 * ED * ED,
                                        wv_b, nullptr, pv16, 1.0f, 2);
    }

    // attention (fully fp16) -> fp16 O
    {
        dim3 grid(NQL / 128, NH, BB);
        attn_mma<<<grid, 256, ATTN_SMEM>>>(pq16, pk16, pv16, lm, ao16);
    }

    // output projection -> fp32 out
    {
        dim3 blk(256);
        dim3 go(ED / GBN, (BB * NQL) / GBM);
        gemm_h<<<go, blk, GEMMH_SMEM>>>(ao16, w16h + 3 * ED * ED, w16l + 3 * ED * ED,
                                        wo_b, out, nullptr, 1.0f, 0);
    }
}